// round 12
// baseline (speedup 1.0000x reference)
#include <cuda_runtime.h>
#include <math.h>

#define Bn 2
#define Sn 2048
#define Dn 1024
#define Hn 16
#define DKn 64
#define FDn 64
#define Mrows (Bn*Sn)

// ---------------- scratch ----------------
__device__ float g_Q[Mrows * Dn];
__device__ float g_K[Mrows * Dn];
__device__ float g_V[Mrows * Dn];        // pair-interleaved: V[r/2][d][r&1]
__device__ float g_A[Mrows * Dn];
__device__ float g_X[Mrows * Dn];        // x rounded to tf32
__device__ float g_Wp[4][Dn * Dn];       // W pair-interleaved: W[k/2][n][k&1], tf32
__device__ float g_Bias[(size_t)Bn * Sn * Sn];   // req.feat^T * log2e

__device__ __forceinline__ unsigned f2tf(float x) {
    unsigned r; asm("cvt.rna.tf32.f32 %0, %1;" : "=r"(r) : "f"(x)); return r;
}
__device__ __forceinline__ float ex2(float x) {
    float r; asm("ex2.approx.f32 %0, %1;" : "=f"(r) : "f"(x)); return r;
}
__device__ __forceinline__ void mma8(float* c, unsigned a0, unsigned a1,
                                     unsigned a2, unsigned a3,
                                     unsigned b0, unsigned b1) {
    asm volatile("mma.sync.aligned.m16n8k8.row.col.f32.tf32.tf32.f32 "
                 "{%0,%1,%2,%3}, {%4,%5,%6,%7}, {%8,%9}, {%0,%1,%2,%3};"
                 : "+f"(c[0]), "+f"(c[1]), "+f"(c[2]), "+f"(c[3])
                 : "r"(a0), "r"(a1), "r"(a2), "r"(a3), "r"(b0), "r"(b1));
}
__device__ __forceinline__ void cp16(unsigned dst, const void* src) {
    asm volatile("cp.async.cg.shared.global [%0], [%1], 16;" :: "r"(dst), "l"(src));
}

// ---------------- pre-round x (tf32) + pair-interleave weights ----------------
__global__ __launch_bounds__(256) void round_inputs(
    const float* __restrict__ x,
    const float* __restrict__ Wq, const float* __restrict__ Wk,
    const float* __restrict__ Wv, const float* __restrict__ Wo)
{
    int idx = blockIdx.x * 256 + threadIdx.x;
    if (idx < 1048576) {
        float4 v = ((const float4*)x)[idx];
        ((uint4*)g_X)[idx] = make_uint4(f2tf(v.x), f2tf(v.y), f2tf(v.z), f2tf(v.w));
    } else {
        int j = idx - 1048576;
        int w = j >> 18;
        int jj = j & 262143;
        int k2 = jj >> 9, nc = jj & 511;
        const float* W = (w == 0) ? Wq : (w == 1) ? Wk : (w == 2) ? Wv : Wo;
        float2 r0 = *(const float2*)&W[(size_t)(2 * k2)     * Dn + 2 * nc];
        float2 r1 = *(const float2*)&W[(size_t)(2 * k2 + 1) * Dn + 2 * nc];
        ((uint4*)g_Wp[w])[(size_t)k2 * 512 + nc] =
            make_uint4(f2tf(r0.x), f2tf(r1.x), f2tf(r0.y), f2tf(r1.y));
    }
}

// ---------------- bias GEMM (fused l2norm): Bias[b] = normalize(R).normalize(F)^T * log2e ----------------
#define FST 72
#define BIAS_SMEM (2 * 128 * FST * 4)
__global__ __launch_bounds__(256) void bias_gemm(
    const float* __restrict__ Rq, const float* __restrict__ Fq, float* __restrict__ Bias)
{
    if (blockIdx.x > blockIdx.y) return;
    extern __shared__ unsigned bsm[];
    unsigned* As = bsm;
    unsigned* Bs = bsm + 128 * FST;

    int tid = threadIdx.x, lane = tid & 31, warp = tid >> 5;
    int g = lane >> 2, t = lane & 3;
    int wm = warp >> 2, wn = warp & 3;
    int i0 = blockIdx.y * 128, j0 = blockIdx.x * 128, bz = blockIdx.z;
    const float* R = Rq + (size_t)bz * Sn * FDn;
    const float* F = Fq + (size_t)bz * Sn * FDn;

    for (int i = tid; i < 128 * 16; i += 256) {
        int r = i >> 4, d4 = (i & 15) * 4;
        *(float4*)((float*)&As[r * FST + d4]) = *(const float4*)&R[(size_t)(i0 + r) * FDn + d4];
        *(float4*)((float*)&Bs[r * FST + d4]) = *(const float4*)&F[(size_t)(j0 + r) * FDn + d4];
    }
    __syncthreads();

    {
        float* rowp = (tid < 128) ? (float*)&As[tid * FST] : (float*)&Bs[(tid - 128) * FST];
        float ss = 0.0f;
        #pragma unroll
        for (int i = 0; i < 16; i++) {
            float4 v = *(const float4*)&rowp[i * 4];
            ss += v.x * v.x + v.y * v.y + v.z * v.z + v.w * v.w;
        }
        float inv = 1.0f / fmaxf(sqrtf(ss), 1e-12f);
        #pragma unroll
        for (int i = 0; i < 16; i++) {
            float4 v = *(const float4*)&rowp[i * 4];
            *(uint4*)&rowp[i * 4] =
                make_uint4(f2tf(v.x * inv), f2tf(v.y * inv), f2tf(v.z * inv), f2tf(v.w * inv));
        }
    }
    __syncthreads();

    float acc[4][4][4];
    #pragma unroll
    for (int i = 0; i < 4; i++)
        #pragma unroll
        for (int j = 0; j < 4; j++)
            #pragma unroll
            for (int r = 0; r < 4; r++) acc[i][j][r] = 0.0f;

    #pragma unroll
    for (int oct = 0; oct < 8; oct++) {
        int kk = oct * 8 + 2 * t;
        #pragma unroll
        for (int mt = 0; mt < 4; mt++) {
            int r = (wm * 64 + mt * 16 + g) * FST + kk;
            uint2 lo = *(const uint2*)&As[r];
            uint2 hi = *(const uint2*)&As[r + 8 * FST];
            #pragma unroll
            for (int nt = 0; nt < 4; nt++) {
                uint2 bb = *(const uint2*)&Bs[(wn * 32 + nt * 8 + g) * FST + kk];
                mma8(acc[mt][nt], lo.x, hi.x, lo.y, hi.y, bb.x, bb.y);
            }
        }
    }

    const float L2E = 1.4426950408889634f;
    float* C = Bias + (size_t)bz * Sn * Sn;
    #pragma unroll
    for (int mt = 0; mt < 4; mt++) {
        int row = i0 + wm * 64 + mt * 16 + g;
        #pragma unroll
        for (int nt = 0; nt < 4; nt++) {
            int col = j0 + wn * 32 + nt * 8 + 2 * t;
            *(float2*)&C[(size_t)row * Sn + col] =
                make_float2(acc[mt][nt][0] * L2E, acc[mt][nt][1] * L2E);
            *(float2*)&C[(size_t)(row + 8) * Sn + col] =
                make_float2(acc[mt][nt][2] * L2E, acc[mt][nt][3] * L2E);
        }
    }
}

// ---------------- tf32 GEMM, cp.async 3-stage, paired-W B operand ----------------
#define AST 40
#define BSTP 264
#define STAGE_A (128 * AST)
#define STAGE_B (16 * BSTP)
#define GSTAGE (STAGE_A + STAGE_B)
#define GEMM_SMEM (3 * GSTAGE * 4)

#define GEMM_CPA(stage, k0) do {                                              \
    unsigned as0 = sbase + (stage) * (GSTAGE * 4);                            \
    unsigned bs0 = as0 + STAGE_A * 4;                                         \
    _Pragma("unroll")                                                         \
    for (int p = 0; p < 4; p++) { int c = tid + 256 * p;                      \
        int r = c >> 3, q = (c & 7) * 4;                                      \
        cp16(as0 + (r * AST + q) * 4, &A[(size_t)(m0 + r) * Dn + (k0) + q]); }\
    _Pragma("unroll")                                                         \
    for (int p = 0; p < 4; p++) { int c = tid + 256 * p;                      \
        int k2 = c >> 6, nc = c & 63;                                         \
        cp16(bs0 + (k2 * BSTP + nc * 4) * 4,                                  \
             &W[(size_t)((k0) / 2 + k2) * 2048 + n0 * 2 + nc * 4]); }         \
    asm volatile("cp.async.commit_group;");                                   \
} while (0)

__global__ __launch_bounds__(256, 2) void gemm_tf32(
    const float* __restrict__ A,
    const float* __restrict__ W0, const float* __restrict__ W1, const float* __restrict__ W2,
    const float* __restrict__ c0p, const float* __restrict__ c1p, const float* __restrict__ c2p,
    float* __restrict__ C0, float* __restrict__ C1, float* __restrict__ C2,
    int roundC, int pairV)
{
    const float* __restrict__ W    = (blockIdx.z == 0) ? W0 : (blockIdx.z == 1) ? W1 : W2;
    const float* __restrict__ bias = (blockIdx.z == 0) ? c0p : (blockIdx.z == 1) ? c1p : c2p;
    float* __restrict__ C          = (blockIdx.z == 0) ? C0 : (blockIdx.z == 1) ? C1 : C2;
    int dopair = pairV && (blockIdx.z == 2);

    extern __shared__ unsigned gsm[];
    unsigned sbase = (unsigned)__cvta_generic_to_shared(gsm);

    int tid = threadIdx.x, lane = tid & 31, warp = tid >> 5;
    int g = lane >> 2, t = lane & 3;
    int wm = warp >> 2, wn = warp & 3;
    int m0 = blockIdx.y * 128, n0 = blockIdx.x * 128;

    float acc[4][4][4];
    #pragma unroll
    for (int i = 0; i < 4; i++)
        #pragma unroll
        for (int j = 0; j < 4; j++)
            #pragma unroll
            for (int r = 0; r < 4; r++) acc[i][j][r] = 0.0f;

    GEMM_CPA(0, 0);
    GEMM_CPA(1, 32);

    for (int it = 0; it < 32; ++it) {
        if (it < 31) asm volatile("cp.async.wait_group 1;");
        else         asm volatile("cp.async.wait_group 0;");
        __syncthreads();
        if (it < 30) {
            int nst = (it + 2) % 3;
            GEMM_CPA(nst, (it + 2) * 32);
        }
        unsigned* Asb = gsm + (it % 3) * GSTAGE;
        unsigned* Bsb = Asb + STAGE_A;
        #pragma unroll
        for (int s = 0; s < 4; ++s) {
            int kb = s * 8 + 2 * t;
            unsigned a[4][4];
            #pragma unroll
            for (int mt = 0; mt < 4; ++mt) {
                int r = (wm * 64 + mt * 16 + g) * AST + kb;
                uint2 lo = *(const uint2*)&Asb[r];
                uint2 hi = *(const uint2*)&Asb[r + 8 * AST];
                a[mt][0] = lo.x; a[mt][1] = hi.x; a[mt][2] = lo.y; a[mt][3] = hi.y;
            }
            #pragma unroll
            for (int nt = 0; nt < 4; ++nt) {
                int col = wn * 32 + nt * 8 + g;
                uint2 qq = *(const uint2*)&Bsb[(s * 4 + t) * BSTP + col * 2];
                #pragma unroll
                for (int mt = 0; mt < 4; ++mt)
                    mma8(acc[mt][nt], a[mt][0], a[mt][1], a[mt][2], a[mt][3], qq.x, qq.y);
            }
        }
    }

    #pragma unroll
    for (int mt = 0; mt < 4; ++mt) {
        int row = m0 + wm * 64 + mt * 16 + g;
        #pragma unroll
        for (int nt = 0; nt < 4; ++nt) {
            int col = n0 + wn * 32 + nt * 8 + 2 * t;
            float b0 = bias[col], b1 = bias[col + 1];
            float x0 = acc[mt][nt][0] + b0, x1 = acc[mt][nt][1] + b1;
            float x2 = acc[mt][nt][2] + b0, x3 = acc[mt][nt][3] + b1;
            if (roundC) {
                x0 = __uint_as_float(f2tf(x0)); x1 = __uint_as_float(f2tf(x1));
                x2 = __uint_as_float(f2tf(x2)); x3 = __uint_as_float(f2tf(x3));
            }
            if (dopair) {
                size_t ba0 = (size_t)(row >> 1) * 2048 + (row & 1);
                size_t ba1 = (size_t)((row + 8) >> 1) * 2048 + ((row + 8) & 1);
                C[ba0 + (size_t)col * 2]       = x0;
                C[ba0 + (size_t)(col + 1) * 2] = x1;
                C[ba1 + (size_t)col * 2]       = x2;
                C[ba1 + (size_t)(col + 1) * 2] = x3;
            } else {
                *(float2*)&C[(size_t)row * Dn + col]       = make_float2(x0, x1);
                *(float2*)&C[(size_t)(row + 8) * Dn + col] = make_float2(x2, x3);
            }
        }
    }
}

// ---------------- tf32 flash attention: q-tile 128, no-max softmax, paired V ----------------
#define KST2 72
#define VSTP 136
#define BST2 40
#define KS2 (32 * KST2)                    // 2304 u32
#define VS2 (16 * VSTP)                    // 2176 u32
#define BS2 (128 * BST2)                   // 5120 u32
#define KVB (KS2 + VS2 + BS2)              // 9600 u32
#define ATT_SMEM (2 * KVB * 4)             // 76800 B -> 2 CTAs/SM

#define ISSUE_KV(stage, kb) do {                                               \
    unsigned ks0 = abase + (stage) * (KVB * 4);                                \
    unsigned vs0 = ks0 + KS2 * 4;                                              \
    unsigned bs0 = vs0 + VS2 * 4;                                              \
    int r2b = (rowoff + (kb)) >> 1;                                            \
    _Pragma("unroll")                                                          \
    for (int p = 0; p < 2; p++) { int c = tid + 256 * p;                       \
        int r = c >> 4, d4 = (c & 15) * 4;                                     \
        cp16(ks0 + (r * KST2 + d4) * 4,                                        \
             &Kp[(size_t)(rowoff + (kb) + r) * Dn + h * DKn + d4]); }          \
    _Pragma("unroll")                                                          \
    for (int p = 0; p < 2; p++) { int c = tid + 256 * p;                       \
        int r2 = c >> 5, q = c & 31;                                           \
        cp16(vs0 + (r2 * VSTP + q * 4) * 4,                                    \
             &Vp[(size_t)(r2b + r2) * 2048 + h * 128 + q * 4]); }              \
    _Pragma("unroll")                                                          \
    for (int p = 0; p < 4; p++) { int c = tid + 256 * p;                       \
        int r = c >> 3, d4 = (c & 7) * 4;                                      \
        cp16(bs0 + (r * BST2 + d4) * 4,                                        \
             &Bbp[(size_t)(qbase + r) * Sn + (kb) + d4]); }                    \
    asm volatile("cp.async.commit_group;");                                    \
} while (0)

__global__ __launch_bounds__(256, 2) void attn_tf32(
    const float* __restrict__ Qp, const float* __restrict__ Kp, const float* __restrict__ Vp,
    const float* __restrict__ Biasp,
    float* __restrict__ O)
{
    extern __shared__ unsigned sm[];
    unsigned abase = (unsigned)__cvta_generic_to_shared(sm);

    int tid = threadIdx.x, lane = tid & 31, warp = tid >> 5;
    int g = lane >> 2, t = lane & 3;
    int qt = 15 - blockIdx.x;                 // biggest tiles first
    int h = blockIdx.y, b = blockIdx.z;
    int qbase = qt * 128, rowoff = b * Sn;
    int wq = warp * 16;
    const float* Bbp = Biasp + (size_t)b * Sn * Sn;

    const float L2E = 1.4426950408889634f;
    // ---- stage Q [128][64] (scaled log2e/8, tf32) in stage-0 area, lift to regs ----
    for (int i = tid; i < 128 * 16; i += 256) {
        int r = i >> 4, d4 = (i & 15) * 4;
        float4 v = *(const float4*)&Qp[(size_t)(rowoff + qbase + r) * Dn + h * DKn + d4];
        float sc = L2E * 0.125f;
        *(uint4*)&sm[r * KST2 + d4] =
            make_uint4(f2tf(v.x * sc), f2tf(v.y * sc), f2tf(v.z * sc), f2tf(v.w * sc));
    }
    __syncthreads();

    unsigned qreg[8][4];
    #pragma unroll
    for (int oct = 0; oct < 8; oct++) {
        int kk = oct * 8 + 2 * t;
        uint2 alo = *(const uint2*)&sm[(wq + g) * KST2 + kk];
        uint2 ahi = *(const uint2*)&sm[(wq + g + 8) * KST2 + kk];
        qreg[oct][0] = alo.x; qreg[oct][1] = ahi.x;
        qreg[oct][2] = alo.y; qreg[oct][3] = ahi.y;
    }
    __syncthreads();                           // staging free; KV pipeline may overwrite

    float o[8][4];
    #pragma unroll
    for (int vt = 0; vt < 8; vt++)
        #pragma unroll
        for (int j = 0; j < 4; j++) o[vt][j] = 0.0f;
    float l0 = 0.0f, l1 = 0.0f;

    int rg0 = qbase + wq + g, rg1 = rg0 + 8;
    int jmax = 4 * qt + 3;                    // kv tiles of 32 covering qbase+127

    ISSUE_KV(0, 0);

    for (int jt = 0; jt <= jmax; jt++) {
        int cur = jt & 1;
        if (jt < jmax) {
            ISSUE_KV(cur ^ 1, (jt + 1) * 32);
            asm volatile("cp.async.wait_group 1;");
        } else {
            asm volatile("cp.async.wait_group 0;");
        }
        __syncthreads();

        unsigned* Ks = sm + cur * KVB;
        unsigned* Vs = Ks + KS2;
        const float* Bf = (const float*)(Vs + VS2);
        int kb = jt * 32;

        // ---- S = Q . K^T (k=64) ----
        float s[4][4];
        #pragma unroll
        for (int nt = 0; nt < 4; nt++)
            #pragma unroll
            for (int j = 0; j < 4; j++) s[nt][j] = 0.0f;

        #pragma unroll
        for (int oct = 0; oct < 8; oct++) {
            int kk = oct * 8 + 2 * t;
            #pragma unroll
            for (int nt = 0; nt < 4; nt++) {
                uint2 bb = *(const uint2*)&Ks[(nt * 8 + g) * KST2 + kk];
                mma8(s[nt], qreg[oct][0], qreg[oct][1], qreg[oct][2], qreg[oct][3],
                     bb.x, bb.y);
            }
        }

        // ---- + bias, causal mask ----
        #pragma unroll
        for (int nt = 0; nt < 4; nt++) {
            float2 b0v = *(const float2*)&Bf[(wq + g) * BST2 + nt * 8 + 2 * t];
            float2 b1v = *(const float2*)&Bf[(wq + g + 8) * BST2 + nt * 8 + 2 * t];
            s[nt][0] += b0v.x; s[nt][1] += b0v.y;
            s[nt][2] += b1v.x; s[nt][3] += b1v.y;
        }
        if (kb + 31 > rg0) {
            #pragma unroll
            for (int nt = 0; nt < 4; nt++) {
                int c0 = kb + nt * 8 + 2 * t, c1 = c0 + 1;
                if (c0 > rg0) s[nt][0] = -1e30f;
                if (c1 > rg0) s[nt][1] = -1e30f;
                if (c0 > rg1) s[nt][2] = -1e30f;
                if (c1 > rg1) s[nt][3] = -1e30f;
            }
        }

        // ---- p = ex2(s), accumulate l per-lane, P->tf32, O += P.V ----
        #pragma unroll
        for (int nt = 0; nt < 4; nt++) {
            s[nt][0] = ex2(s[nt][0]);
            s[nt][1] = ex2(s[nt][1]);
            s[nt][2] = ex2(s[nt][2]);
            s[nt][3] = ex2(s[nt][3]);
            l0 += s[nt][0] + s[nt][1];
            l1 += s[nt][2] + s[nt][3];
            #pragma unroll
            for (int j = 0; j < 4; j++)
                s[nt][j] = __uint_as_float(f2tf(s[nt][j]));
        }

        #pragma unroll
        for (int oct = 0; oct < 4; oct++) {
            unsigned pa0 = __float_as_uint(s[oct][0]);
            unsigned pa1 = __float_as_uint(s[oct][2]);
            unsigned pa2 = __float_as_uint(s[oct][1]);
            unsigned pa3 = __float_as_uint(s[oct][3]);
            int r2row = oct * 4 + t;
            #pragma unroll
            for (int vt = 0; vt < 8; vt++) {
                uint2 bb = *(const uint2*)&Vs[r2row * VSTP + (vt * 8 + g) * 2];
                mma8(o[vt], pa0, pa1, pa2, pa3, bb.x, bb.y);
            }
        }
        __syncthreads();
    }

    // ---- epilogue: reduce l over the 4-lane t-group, normalize, store ----
    l0 += __shfl_xor_sync(0xffffffffu, l0, 1);
    l0 += __shfl_xor_sync(0xffffffffu, l0, 2);
    l1 += __shfl_xor_sync(0xffffffffu, l1, 1);
    l1 += __shfl_xor_sync(0xffffffffu, l1, 2);
    float inv0 = 1.0f / l0, inv1 = 1.0f / l1;
    int r0 = rowoff + rg0, r1 = rowoff + rg1;
    #pragma unroll
    for (int vt = 0; vt < 8; vt++) {
        int col = h * DKn + vt * 8 + 2 * t;
        *(uint2*)&O[(size_t)r0 * Dn + col] =
            make_uint2(f2tf(o[vt][0] * inv0), f2tf(o[vt][1] * inv0));
        *(uint2*)&O[(size_t)r1 * Dn + col] =
            make_uint2(f2tf(o[vt][2] * inv1), f2tf(o[vt][3] * inv1));
    }
}

// ---------------- launch ----------------
extern "C" void kernel_launch(void* const* d_in, const int* in_sizes, int n_in,
                              void* d_out, int out_size)
{
    const float* x    = (const float*)d_in[0];
    const float* feat = (const float*)d_in[1];
    const float* req  = (const float*)d_in[2];
    const float* Wq   = (const float*)d_in[3];
    const float* bq   = (const float*)d_in[4];
    const float* Wk   = (const float*)d_in[5];
    const float* bk   = (const float*)d_in[6];
    const float* Wv   = (const float*)d_in[7];
    const float* bv   = (const float*)d_in[8];
    const float* Wo   = (const float*)d_in[9];
    const float* bo   = (const float*)d_in[10];
    float* out = (float*)d_out;

    float *gQ, *gK, *gV, *gA, *gX, *gWp, *gB;
    cudaGetSymbolAddress((void**)&gQ,  g_Q);
    cudaGetSymbolAddress((void**)&gK,  g_K);
    cudaGetSymbolAddress((void**)&gV,  g_V);
    cudaGetSymbolAddress((void**)&gA,  g_A);
    cudaGetSymbolAddress((void**)&gX,  g_X);
    cudaGetSymbolAddress((void**)&gWp, g_Wp);
    cudaGetSymbolAddress((void**)&gB,  g_Bias);
    const float* gWpq = gWp;
    const float* gWpk = gWp + Dn * Dn;
    const float* gWpv = gWp + 2 * Dn * Dn;
    const float* gWpo = gWp + 3 * Dn * Dn;

    cudaFuncSetAttribute(gemm_tf32,
                         cudaFuncAttributeMaxDynamicSharedMemorySize, GEMM_SMEM);
    cudaFuncSetAttribute(attn_tf32,
                         cudaFuncAttributeMaxDynamicSharedMemorySize, ATT_SMEM);
    cudaFuncSetAttribute(bias_gemm,
                         cudaFuncAttributeMaxDynamicSharedMemorySize, BIAS_SMEM);

    round_inputs<<<8192, 256>>>(x, Wq, Wk, Wv, Wo);
    bias_gemm<<<dim3(16, 16, 2), 256, BIAS_SMEM>>>(req, feat, gB);

    gemm_tf32<<<dim3(8, 32, 3), 256, GEMM_SMEM>>>(
        gX, gWpq, gWpk, gWpv, bq, bk, bv, gQ, gK, gV, 1, 1);

    attn_tf32<<<dim3(16, Hn, Bn), 256, ATT_SMEM>>>(gQ, gK, gV, gB, gA);

    gemm_tf32<<<dim3(8, 32, 1), 256, GEMM_SMEM>>>(
        gA, gWpo, gWpo, gWpo, bo, bo, bo, out, out, out, 0, 0);
}

// round 13
// speedup vs baseline: 1.0363x; 1.0363x over previous
#include <cuda_runtime.h>
#include <math.h>

#define Bn 2
#define Sn 2048
#define Dn 1024
#define Hn 16
#define DKn 64
#define FDn 64
#define Mrows (Bn*Sn)

// ---------------- scratch ----------------
__device__ float g_Q[Mrows * Dn];
__device__ float g_K[Mrows * Dn];
__device__ float g_V[Mrows * Dn];        // pair-interleaved: V[r/2][d][r&1]
__device__ float g_A[Mrows * Dn];
__device__ float g_X[Mrows * Dn];        // x rounded to tf32
__device__ float g_Wp[4][Dn * Dn];       // W pair-interleaved: W[k/2][n][k&1], tf32
__device__ float g_Bias[(size_t)Bn * Sn * Sn];   // req.feat^T * log2e

__device__ __forceinline__ unsigned f2tf(float x) {
    unsigned r; asm("cvt.rna.tf32.f32 %0, %1;" : "=r"(r) : "f"(x)); return r;
}
__device__ __forceinline__ float ex2(float x) {
    float r; asm("ex2.approx.f32 %0, %1;" : "=f"(r) : "f"(x)); return r;
}
__device__ __forceinline__ void mma8(float* c, unsigned a0, unsigned a1,
                                     unsigned a2, unsigned a3,
                                     unsigned b0, unsigned b1) {
    asm volatile("mma.sync.aligned.m16n8k8.row.col.f32.tf32.tf32.f32 "
                 "{%0,%1,%2,%3}, {%4,%5,%6,%7}, {%8,%9}, {%0,%1,%2,%3};"
                 : "+f"(c[0]), "+f"(c[1]), "+f"(c[2]), "+f"(c[3])
                 : "r"(a0), "r"(a1), "r"(a2), "r"(a3), "r"(b0), "r"(b1));
}
__device__ __forceinline__ void cp16(unsigned dst, const void* src) {
    asm volatile("cp.async.cg.shared.global [%0], [%1], 16;" :: "r"(dst), "l"(src));
}

// ---------------- pre-round x (tf32) + pair-interleave weights ----------------
__global__ __launch_bounds__(256) void round_inputs(
    const float* __restrict__ x,
    const float* __restrict__ Wq, const float* __restrict__ Wk,
    const float* __restrict__ Wv, const float* __restrict__ Wo)
{
    int idx = blockIdx.x * 256 + threadIdx.x;
    if (idx < 1048576) {
        float4 v = ((const float4*)x)[idx];
        ((uint4*)g_X)[idx] = make_uint4(f2tf(v.x), f2tf(v.y), f2tf(v.z), f2tf(v.w));
    } else {
        int j = idx - 1048576;
        int w = j >> 18;
        int jj = j & 262143;
        int k2 = jj >> 9, nc = jj & 511;
        const float* W = (w == 0) ? Wq : (w == 1) ? Wk : (w == 2) ? Wv : Wo;
        float2 r0 = *(const float2*)&W[(size_t)(2 * k2)     * Dn + 2 * nc];
        float2 r1 = *(const float2*)&W[(size_t)(2 * k2 + 1) * Dn + 2 * nc];
        ((uint4*)g_Wp[w])[(size_t)k2 * 512 + nc] =
            make_uint4(f2tf(r0.x), f2tf(r1.x), f2tf(r0.y), f2tf(r1.y));
    }
}

// ---------------- bias GEMM (fused l2norm): Bias[b] = normalize(R).normalize(F)^T * log2e ----------------
#define FST 72
#define BIAS_SMEM (2 * 128 * FST * 4)
__global__ __launch_bounds__(256) void bias_gemm(
    const float* __restrict__ Rq, const float* __restrict__ Fq, float* __restrict__ Bias)
{
    if (blockIdx.x > blockIdx.y) return;
    extern __shared__ unsigned bsm[];
    unsigned* As = bsm;
    unsigned* Bs = bsm + 128 * FST;

    int tid = threadIdx.x, lane = tid & 31, warp = tid >> 5;
    int g = lane >> 2, t = lane & 3;
    int wm = warp >> 2, wn = warp & 3;
    int i0 = blockIdx.y * 128, j0 = blockIdx.x * 128, bz = blockIdx.z;
    const float* R = Rq + (size_t)bz * Sn * FDn;
    const float* F = Fq + (size_t)bz * Sn * FDn;

    for (int i = tid; i < 128 * 16; i += 256) {
        int r = i >> 4, d4 = (i & 15) * 4;
        *(float4*)((float*)&As[r * FST + d4]) = *(const float4*)&R[(size_t)(i0 + r) * FDn + d4];
        *(float4*)((float*)&Bs[r * FST + d4]) = *(const float4*)&F[(size_t)(j0 + r) * FDn + d4];
    }
    __syncthreads();

    {
        float* rowp = (tid < 128) ? (float*)&As[tid * FST] : (float*)&Bs[(tid - 128) * FST];
        float ss = 0.0f;
        #pragma unroll
        for (int i = 0; i < 16; i++) {
            float4 v = *(const float4*)&rowp[i * 4];
            ss += v.x * v.x + v.y * v.y + v.z * v.z + v.w * v.w;
        }
        float inv = 1.0f / fmaxf(sqrtf(ss), 1e-12f);
        #pragma unroll
        for (int i = 0; i < 16; i++) {
            float4 v = *(const float4*)&rowp[i * 4];
            *(uint4*)&rowp[i * 4] =
                make_uint4(f2tf(v.x * inv), f2tf(v.y * inv), f2tf(v.z * inv), f2tf(v.w * inv));
        }
    }
    __syncthreads();

    float acc[4][4][4];
    #pragma unroll
    for (int i = 0; i < 4; i++)
        #pragma unroll
        for (int j = 0; j < 4; j++)
            #pragma unroll
            for (int r = 0; r < 4; r++) acc[i][j][r] = 0.0f;

    #pragma unroll
    for (int oct = 0; oct < 8; oct++) {
        int kk = oct * 8 + 2 * t;
        #pragma unroll
        for (int mt = 0; mt < 4; mt++) {
            int r = (wm * 64 + mt * 16 + g) * FST + kk;
            uint2 lo = *(const uint2*)&As[r];
            uint2 hi = *(const uint2*)&As[r + 8 * FST];
            #pragma unroll
            for (int nt = 0; nt < 4; nt++) {
                uint2 bb = *(const uint2*)&Bs[(wn * 32 + nt * 8 + g) * FST + kk];
                mma8(acc[mt][nt], lo.x, hi.x, lo.y, hi.y, bb.x, bb.y);
            }
        }
    }

    const float L2E = 1.4426950408889634f;
    float* C = Bias + (size_t)bz * Sn * Sn;
    #pragma unroll
    for (int mt = 0; mt < 4; mt++) {
        int row = i0 + wm * 64 + mt * 16 + g;
        #pragma unroll
        for (int nt = 0; nt < 4; nt++) {
            int col = j0 + wn * 32 + nt * 8 + 2 * t;
            *(float2*)&C[(size_t)row * Sn + col] =
                make_float2(acc[mt][nt][0] * L2E, acc[mt][nt][1] * L2E);
            *(float2*)&C[(size_t)(row + 8) * Sn + col] =
                make_float2(acc[mt][nt][2] * L2E, acc[mt][nt][3] * L2E);
        }
    }
}

// ---------------- tf32 GEMM, cp.async 3-stage, paired-W B operand ----------------
#define AST 40
#define BSTP 264
#define STAGE_A (128 * AST)
#define STAGE_B (16 * BSTP)
#define GSTAGE (STAGE_A + STAGE_B)
#define GEMM_SMEM (3 * GSTAGE * 4)

#define GEMM_CPA(stage, k0) do {                                              \
    unsigned as0 = sbase + (stage) * (GSTAGE * 4);                            \
    unsigned bs0 = as0 + STAGE_A * 4;                                         \
    _Pragma("unroll")                                                         \
    for (int p = 0; p < 4; p++) { int c = tid + 256 * p;                      \
        int r = c >> 3, q = (c & 7) * 4;                                      \
        cp16(as0 + (r * AST + q) * 4, &A[(size_t)(m0 + r) * Dn + (k0) + q]); }\
    _Pragma("unroll")                                                         \
    for (int p = 0; p < 4; p++) { int c = tid + 256 * p;                      \
        int k2 = c >> 6, nc = c & 63;                                         \
        cp16(bs0 + (k2 * BSTP + nc * 4) * 4,                                  \
             &W[(size_t)((k0) / 2 + k2) * 2048 + n0 * 2 + nc * 4]); }         \
    asm volatile("cp.async.commit_group;");                                   \
} while (0)

__global__ __launch_bounds__(256, 2) void gemm_tf32(
    const float* __restrict__ A,
    const float* __restrict__ W0, const float* __restrict__ W1, const float* __restrict__ W2,
    const float* __restrict__ c0p, const float* __restrict__ c1p, const float* __restrict__ c2p,
    float* __restrict__ C0, float* __restrict__ C1, float* __restrict__ C2,
    int roundC, int pairV)
{
    const float* __restrict__ W    = (blockIdx.z == 0) ? W0 : (blockIdx.z == 1) ? W1 : W2;
    const float* __restrict__ bias = (blockIdx.z == 0) ? c0p : (blockIdx.z == 1) ? c1p : c2p;
    float* __restrict__ C          = (blockIdx.z == 0) ? C0 : (blockIdx.z == 1) ? C1 : C2;
    int dopair = pairV && (blockIdx.z == 2);

    extern __shared__ unsigned gsm[];
    unsigned sbase = (unsigned)__cvta_generic_to_shared(gsm);

    int tid = threadIdx.x, lane = tid & 31, warp = tid >> 5;
    int g = lane >> 2, t = lane & 3;
    int wm = warp >> 2, wn = warp & 3;
    int m0 = blockIdx.y * 128, n0 = blockIdx.x * 128;

    float acc[4][4][4];
    #pragma unroll
    for (int i = 0; i < 4; i++)
        #pragma unroll
        for (int j = 0; j < 4; j++)
            #pragma unroll
            for (int r = 0; r < 4; r++) acc[i][j][r] = 0.0f;

    GEMM_CPA(0, 0);
    GEMM_CPA(1, 32);

    for (int it = 0; it < 32; ++it) {
        if (it < 31) asm volatile("cp.async.wait_group 1;");
        else         asm volatile("cp.async.wait_group 0;");
        __syncthreads();
        if (it < 30) {
            int nst = (it + 2) % 3;
            GEMM_CPA(nst, (it + 2) * 32);
        }
        unsigned* Asb = gsm + (it % 3) * GSTAGE;
        unsigned* Bsb = Asb + STAGE_A;
        #pragma unroll
        for (int s = 0; s < 4; ++s) {
            int kb = s * 8 + 2 * t;
            unsigned a[4][4];
            #pragma unroll
            for (int mt = 0; mt < 4; ++mt) {
                int r = (wm * 64 + mt * 16 + g) * AST + kb;
                uint2 lo = *(const uint2*)&Asb[r];
                uint2 hi = *(const uint2*)&Asb[r + 8 * AST];
                a[mt][0] = lo.x; a[mt][1] = hi.x; a[mt][2] = lo.y; a[mt][3] = hi.y;
            }
            #pragma unroll
            for (int nt = 0; nt < 4; ++nt) {
                int col = wn * 32 + nt * 8 + g;
                uint2 qq = *(const uint2*)&Bsb[(s * 4 + t) * BSTP + col * 2];
                #pragma unroll
                for (int mt = 0; mt < 4; ++mt)
                    mma8(acc[mt][nt], a[mt][0], a[mt][1], a[mt][2], a[mt][3], qq.x, qq.y);
            }
        }
    }

    #pragma unroll
    for (int mt = 0; mt < 4; ++mt) {
        int row = m0 + wm * 64 + mt * 16 + g;
        #pragma unroll
        for (int nt = 0; nt < 4; ++nt) {
            int col = n0 + wn * 32 + nt * 8 + 2 * t;
            float b0 = bias[col], b1 = bias[col + 1];
            float x0 = acc[mt][nt][0] + b0, x1 = acc[mt][nt][1] + b1;
            float x2 = acc[mt][nt][2] + b0, x3 = acc[mt][nt][3] + b1;
            if (roundC) {
                x0 = __uint_as_float(f2tf(x0)); x1 = __uint_as_float(f2tf(x1));
                x2 = __uint_as_float(f2tf(x2)); x3 = __uint_as_float(f2tf(x3));
            }
            if (dopair) {
                size_t ba0 = (size_t)(row >> 1) * 2048 + (row & 1);
                size_t ba1 = (size_t)((row + 8) >> 1) * 2048 + ((row + 8) & 1);
                C[ba0 + (size_t)col * 2]       = x0;
                C[ba0 + (size_t)(col + 1) * 2] = x1;
                C[ba1 + (size_t)col * 2]       = x2;
                C[ba1 + (size_t)(col + 1) * 2] = x3;
            } else {
                *(float2*)&C[(size_t)row * Dn + col]       = make_float2(x0, x1);
                *(float2*)&C[(size_t)(row + 8) * Dn + col] = make_float2(x2, x3);
            }
        }
    }
}

// ---------------- tf32 flash attention: q64/128thr, no-max softmax, bias via LDG ----------------
#define KST2 72
#define VSTP 136
#define KS2 (32 * KST2)                    // 2304 u32
#define VS2 (16 * VSTP)                    // 2176 u32
#define KVB (KS2 + VS2)                    // 4480 u32
#define ATT_SMEM (2 * KVB * 4)             // 35840 B

#define ISSUE_KV(stage, kb) do {                                               \
    unsigned ks0 = abase + (stage) * (KVB * 4);                                \
    unsigned vs0 = ks0 + KS2 * 4;                                              \
    int r2b = (rowoff + (kb)) >> 1;                                            \
    _Pragma("unroll")                                                          \
    for (int p = 0; p < 4; p++) { int c = tid + 128 * p;                       \
        int r = c >> 4, d4 = (c & 15) * 4;                                     \
        cp16(ks0 + (r * KST2 + d4) * 4,                                        \
             &Kp[(size_t)(rowoff + (kb) + r) * Dn + h * DKn + d4]); }          \
    _Pragma("unroll")                                                          \
    for (int p = 0; p < 4; p++) { int c = tid + 128 * p;                       \
        int r2 = c >> 5, q = c & 31;                                           \
        cp16(vs0 + (r2 * VSTP + q * 4) * 4,                                    \
             &Vp[(size_t)(r2b + r2) * 2048 + h * 128 + q * 4]); }              \
    asm volatile("cp.async.commit_group;");                                    \
} while (0)

__global__ __launch_bounds__(128, 4) void attn_tf32(
    const float* __restrict__ Qp, const float* __restrict__ Kp, const float* __restrict__ Vp,
    const float* __restrict__ Biasp,
    float* __restrict__ O)
{
    extern __shared__ unsigned sm[];
    unsigned abase = (unsigned)__cvta_generic_to_shared(sm);

    int tid = threadIdx.x, lane = tid & 31, warp = tid >> 5;
    int g = lane >> 2, t = lane & 3;
    int qt = 31 - blockIdx.x;
    int h = blockIdx.y, b = blockIdx.z;
    int qbase = qt * 64, rowoff = b * Sn;
    int wq = warp * 16;
    // per-thread bias row pointers (float2 granularity)
    const float2* Bg0 = (const float2*)(Biasp + (size_t)b * Sn * Sn
                                        + (size_t)(qbase + wq + g) * Sn) + t;
    const float2* Bg1 = Bg0 + 4 * Sn / 2 * 2;   // row +8 => +8*Sn floats = +4*Sn float2

    const float L2E = 1.4426950408889634f;
    for (int i = tid; i < 64 * 16; i += 128) {
        int r = i >> 4, d4 = (i & 15) * 4;
        float4 v = *(const float4*)&Qp[(size_t)(rowoff + qbase + r) * Dn + h * DKn + d4];
        float sc = L2E * 0.125f;
        *(uint4*)&sm[r * KST2 + d4] =
            make_uint4(f2tf(v.x * sc), f2tf(v.y * sc), f2tf(v.z * sc), f2tf(v.w * sc));
    }
    __syncthreads();

    unsigned qreg[8][4];
    #pragma unroll
    for (int oct = 0; oct < 8; oct++) {
        int kk = oct * 8 + 2 * t;
        uint2 alo = *(const uint2*)&sm[(wq + g) * KST2 + kk];
        uint2 ahi = *(const uint2*)&sm[(wq + g + 8) * KST2 + kk];
        qreg[oct][0] = alo.x; qreg[oct][1] = ahi.x;
        qreg[oct][2] = alo.y; qreg[oct][3] = ahi.y;
    }
    __syncthreads();

    float o[8][4];
    #pragma unroll
    for (int vt = 0; vt < 8; vt++)
        #pragma unroll
        for (int j = 0; j < 4; j++) o[vt][j] = 0.0f;
    float l0 = 0.0f, l1 = 0.0f;

    int rg0 = qbase + wq + g, rg1 = rg0 + 8;
    int jmax = 2 * qt + 1;

    ISSUE_KV(0, 0);

    for (int jt = 0; jt <= jmax; jt++) {
        int cur = jt & 1;
        int kb = jt * 32;
        if (jt < jmax) {
            ISSUE_KV(cur ^ 1, (jt + 1) * 32);
            asm volatile("cp.async.wait_group 1;");
        } else {
            asm volatile("cp.async.wait_group 0;");
        }
        __syncthreads();

        // ---- prefetch bias fragment for THIS iter from global (L2-hot) ----
        float2 bv0[4], bv1[4];
        {
            int c2 = kb >> 1;   // float2 col index of kb
            #pragma unroll
            for (int nt = 0; nt < 4; nt++) {
                bv0[nt] = __ldg(Bg0 + c2 + nt * 4);
                bv1[nt] = __ldg(Bg1 + c2 + nt * 4);
            }
        }

        unsigned* Ks = sm + cur * KVB;
        unsigned* Vs = Ks + KS2;

        // ---- S = Q . K^T (k=64) ----
        float s[4][4];
        #pragma unroll
        for (int nt = 0; nt < 4; nt++)
            #pragma unroll
            for (int j = 0; j < 4; j++) s[nt][j] = 0.0f;

        #pragma unroll
        for (int oct = 0; oct < 8; oct++) {
            int kk = oct * 8 + 2 * t;
            #pragma unroll
            for (int nt = 0; nt < 4; nt++) {
                uint2 bb = *(const uint2*)&Ks[(nt * 8 + g) * KST2 + kk];
                mma8(s[nt], qreg[oct][0], qreg[oct][1], qreg[oct][2], qreg[oct][3],
                     bb.x, bb.y);
            }
        }

        // ---- + bias (regs), causal mask ----
        #pragma unroll
        for (int nt = 0; nt < 4; nt++) {
            s[nt][0] += bv0[nt].x; s[nt][1] += bv0[nt].y;
            s[nt][2] += bv1[nt].x; s[nt][3] += bv1[nt].y;
        }
        if (kb + 31 > rg0) {
            #pragma unroll
            for (int nt = 0; nt < 4; nt++) {
                int c0 = kb + nt * 8 + 2 * t, c1 = c0 + 1;
                if (c0 > rg0) s[nt][0] = -1e30f;
                if (c1 > rg0) s[nt][1] = -1e30f;
                if (c0 > rg1) s[nt][2] = -1e30f;
                if (c1 > rg1) s[nt][3] = -1e30f;
            }
        }

        // ---- p = ex2(s), accumulate l per-lane, P->tf32, O += P.V ----
        #pragma unroll
        for (int nt = 0; nt < 4; nt++) {
            s[nt][0] = ex2(s[nt][0]);
            s[nt][1] = ex2(s[nt][1]);
            s[nt][2] = ex2(s[nt][2]);
            s[nt][3] = ex2(s[nt][3]);
            l0 += s[nt][0] + s[nt][1];
            l1 += s[nt][2] + s[nt][3];
            #pragma unroll
            for (int j = 0; j < 4; j++)
                s[nt][j] = __uint_as_float(f2tf(s[nt][j]));
        }

        #pragma unroll
        for (int oct = 0; oct < 4; oct++) {
            unsigned pa0 = __float_as_uint(s[oct][0]);
            unsigned pa1 = __float_as_uint(s[oct][2]);
            unsigned pa2 = __float_as_uint(s[oct][1]);
            unsigned pa3 = __float_as_uint(s[oct][3]);
            int r2row = oct * 4 + t;
            #pragma unroll
            for (int vt = 0; vt < 8; vt++) {
                uint2 bb = *(const uint2*)&Vs[r2row * VSTP + (vt * 8 + g) * 2];
                mma8(o[vt], pa0, pa1, pa2, pa3, bb.x, bb.y);
            }
        }
        __syncthreads();
    }

    // ---- epilogue ----
    l0 += __shfl_xor_sync(0xffffffffu, l0, 1);
    l0 += __shfl_xor_sync(0xffffffffu, l0, 2);
    l1 += __shfl_xor_sync(0xffffffffu, l1, 1);
    l1 += __shfl_xor_sync(0xffffffffu, l1, 2);
    float inv0 = 1.0f / l0, inv1 = 1.0f / l1;
    int r0 = rowoff + rg0, r1 = rowoff + rg1;
    #pragma unroll
    for (int vt = 0; vt < 8; vt++) {
        int col = h * DKn + vt * 8 + 2 * t;
        *(uint2*)&O[(size_t)r0 * Dn + col] =
            make_uint2(f2tf(o[vt][0] * inv0), f2tf(o[vt][1] * inv0));
        *(uint2*)&O[(size_t)r1 * Dn + col] =
            make_uint2(f2tf(o[vt][2] * inv1), f2tf(o[vt][3] * inv1));
    }
}

// ---------------- launch ----------------
extern "C" void kernel_launch(void* const* d_in, const int* in_sizes, int n_in,
                              void* d_out, int out_size)
{
    const float* x    = (const float*)d_in[0];
    const float* feat = (const float*)d_in[1];
    const float* req  = (const float*)d_in[2];
    const float* Wq   = (const float*)d_in[3];
    const float* bq   = (const float*)d_in[4];
    const float* Wk   = (const float*)d_in[5];
    const float* bk   = (const float*)d_in[6];
    const float* Wv   = (const float*)d_in[7];
    const float* bv   = (const float*)d_in[8];
    const float* Wo   = (const float*)d_in[9];
    const float* bo   = (const float*)d_in[10];
    float* out = (float*)d_out;

    float *gQ, *gK, *gV, *gA, *gX, *gWp, *gB;
    cudaGetSymbolAddress((void**)&gQ,  g_Q);
    cudaGetSymbolAddress((void**)&gK,  g_K);
    cudaGetSymbolAddress((void**)&gV,  g_V);
    cudaGetSymbolAddress((void**)&gA,  g_A);
    cudaGetSymbolAddress((void**)&gX,  g_X);
    cudaGetSymbolAddress((void**)&gWp, g_Wp);
    cudaGetSymbolAddress((void**)&gB,  g_Bias);
    const float* gWpq = gWp;
    const float* gWpk = gWp + Dn * Dn;
    const float* gWpv = gWp + 2 * Dn * Dn;
    const float* gWpo = gWp + 3 * Dn * Dn;

    cudaFuncSetAttribute(gemm_tf32,
                         cudaFuncAttributeMaxDynamicSharedMemorySize, GEMM_SMEM);
    cudaFuncSetAttribute(attn_tf32,
                         cudaFuncAttributeMaxDynamicSharedMemorySize, ATT_SMEM);
    cudaFuncSetAttribute(bias_gemm,
                         cudaFuncAttributeMaxDynamicSharedMemorySize, BIAS_SMEM);

    round_inputs<<<8192, 256>>>(x, Wq, Wk, Wv, Wo);
    bias_gemm<<<dim3(16, 16, 2), 256, BIAS_SMEM>>>(req, feat, gB);

    gemm_tf32<<<dim3(8, 32, 3), 256, GEMM_SMEM>>>(
        gX, gWpq, gWpk, gWpv, bq, bk, bv, gQ, gK, gV, 1, 1);

    attn_tf32<<<dim3(32, Hn, Bn), 128, ATT_SMEM>>>(gQ, gK, gV, gB, gA);

    gemm_tf32<<<dim3(8, 32, 1), 256, GEMM_SMEM>>>(
        gA, gWpo, gWpo, gWpo, bo, bo, bo, out, out, out, 0, 0);
}

// round 14
// speedup vs baseline: 1.0707x; 1.0331x over previous
#include <cuda_runtime.h>
#include <math.h>

#define Bn 2
#define Sn 2048
#define Dn 1024
#define Hn 16
#define DKn 64
#define FDn 64
#define Mrows (Bn*Sn)

// ---------------- scratch ----------------
__device__ float g_Q[Mrows * Dn];
__device__ float g_K[Mrows * Dn];
__device__ float g_V[Mrows * Dn];        // pair-interleaved: V[r/2][d][r&1]
__device__ float g_A[Mrows * Dn];
__device__ float g_X[Mrows * Dn];        // x rounded to tf32
__device__ float g_Wp[4][Dn * Dn];       // W pair-interleaved: W[k/2][n][k&1], tf32
__device__ float g_Bias[(size_t)Bn * Sn * Sn];   // req.feat^T * log2e

__device__ __forceinline__ unsigned f2tf(float x) {
    unsigned r; asm("cvt.rna.tf32.f32 %0, %1;" : "=r"(r) : "f"(x)); return r;
}
__device__ __forceinline__ float ex2(float x) {
    float r; asm("ex2.approx.f32 %0, %1;" : "=f"(r) : "f"(x)); return r;
}
__device__ __forceinline__ void mma8(float* c, unsigned a0, unsigned a1,
                                     unsigned a2, unsigned a3,
                                     unsigned b0, unsigned b1) {
    asm volatile("mma.sync.aligned.m16n8k8.row.col.f32.tf32.tf32.f32 "
                 "{%0,%1,%2,%3}, {%4,%5,%6,%7}, {%8,%9}, {%0,%1,%2,%3};"
                 : "+f"(c[0]), "+f"(c[1]), "+f"(c[2]), "+f"(c[3])
                 : "r"(a0), "r"(a1), "r"(a2), "r"(a3), "r"(b0), "r"(b1));
}
__device__ __forceinline__ void cp16(unsigned dst, const void* src) {
    asm volatile("cp.async.cg.shared.global [%0], [%1], 16;" :: "r"(dst), "l"(src));
}

// ---------------- pre-round x (tf32) + pair-interleave weights ----------------
__global__ __launch_bounds__(256) void round_inputs(
    const float* __restrict__ x,
    const float* __restrict__ Wq, const float* __restrict__ Wk,
    const float* __restrict__ Wv, const float* __restrict__ Wo)
{
    int idx = blockIdx.x * 256 + threadIdx.x;
    if (idx < 1048576) {
        float4 v = ((const float4*)x)[idx];
        ((uint4*)g_X)[idx] = make_uint4(f2tf(v.x), f2tf(v.y), f2tf(v.z), f2tf(v.w));
    } else {
        int j = idx - 1048576;
        int w = j >> 18;
        int jj = j & 262143;
        int k2 = jj >> 9, nc = jj & 511;
        const float* W = (w == 0) ? Wq : (w == 1) ? Wk : (w == 2) ? Wv : Wo;
        float2 r0 = *(const float2*)&W[(size_t)(2 * k2)     * Dn + 2 * nc];
        float2 r1 = *(const float2*)&W[(size_t)(2 * k2 + 1) * Dn + 2 * nc];
        ((uint4*)g_Wp[w])[(size_t)k2 * 512 + nc] =
            make_uint4(f2tf(r0.x), f2tf(r1.x), f2tf(r0.y), f2tf(r1.y));
    }
}

// ---------------- bias GEMM (fused l2norm): Bias[b] = normalize(R).normalize(F)^T * log2e ----------------
#define FST 72
#define BIAS_SMEM (2 * 128 * FST * 4)
__global__ __launch_bounds__(256) void bias_gemm(
    const float* __restrict__ Rq, const float* __restrict__ Fq, float* __restrict__ Bias)
{
    if (blockIdx.x > blockIdx.y) return;
    extern __shared__ unsigned bsm[];
    unsigned* As = bsm;
    unsigned* Bs = bsm + 128 * FST;

    int tid = threadIdx.x, lane = tid & 31, warp = tid >> 5;
    int g = lane >> 2, t = lane & 3;
    int wm = warp >> 2, wn = warp & 3;
    int i0 = blockIdx.y * 128, j0 = blockIdx.x * 128, bz = blockIdx.z;
    const float* R = Rq + (size_t)bz * Sn * FDn;
    const float* F = Fq + (size_t)bz * Sn * FDn;

    for (int i = tid; i < 128 * 16; i += 256) {
        int r = i >> 4, d4 = (i & 15) * 4;
        *(float4*)((float*)&As[r * FST + d4]) = *(const float4*)&R[(size_t)(i0 + r) * FDn + d4];
        *(float4*)((float*)&Bs[r * FST + d4]) = *(const float4*)&F[(size_t)(j0 + r) * FDn + d4];
    }
    __syncthreads();

    {
        float* rowp = (tid < 128) ? (float*)&As[tid * FST] : (float*)&Bs[(tid - 128) * FST];
        float ss = 0.0f;
        #pragma unroll
        for (int i = 0; i < 16; i++) {
            float4 v = *(const float4*)&rowp[i * 4];
            ss += v.x * v.x + v.y * v.y + v.z * v.z + v.w * v.w;
        }
        float inv = 1.0f / fmaxf(sqrtf(ss), 1e-12f);
        #pragma unroll
        for (int i = 0; i < 16; i++) {
            float4 v = *(const float4*)&rowp[i * 4];
            *(uint4*)&rowp[i * 4] =
                make_uint4(f2tf(v.x * inv), f2tf(v.y * inv), f2tf(v.z * inv), f2tf(v.w * inv));
        }
    }
    __syncthreads();

    float acc[4][4][4];
    #pragma unroll
    for (int i = 0; i < 4; i++)
        #pragma unroll
        for (int j = 0; j < 4; j++)
            #pragma unroll
            for (int r = 0; r < 4; r++) acc[i][j][r] = 0.0f;

    #pragma unroll
    for (int oct = 0; oct < 8; oct++) {
        int kk = oct * 8 + 2 * t;
        #pragma unroll
        for (int mt = 0; mt < 4; mt++) {
            int r = (wm * 64 + mt * 16 + g) * FST + kk;
            uint2 lo = *(const uint2*)&As[r];
            uint2 hi = *(const uint2*)&As[r + 8 * FST];
            #pragma unroll
            for (int nt = 0; nt < 4; nt++) {
                uint2 bb = *(const uint2*)&Bs[(wn * 32 + nt * 8 + g) * FST + kk];
                mma8(acc[mt][nt], lo.x, hi.x, lo.y, hi.y, bb.x, bb.y);
            }
        }
    }

    const float L2E = 1.4426950408889634f;
    float* C = Bias + (size_t)bz * Sn * Sn;
    #pragma unroll
    for (int mt = 0; mt < 4; mt++) {
        int row = i0 + wm * 64 + mt * 16 + g;
        #pragma unroll
        for (int nt = 0; nt < 4; nt++) {
            int col = j0 + wn * 32 + nt * 8 + 2 * t;
            *(float2*)&C[(size_t)row * Sn + col] =
                make_float2(acc[mt][nt][0] * L2E, acc[mt][nt][1] * L2E);
            *(float2*)&C[(size_t)(row + 8) * Sn + col] =
                make_float2(acc[mt][nt][2] * L2E, acc[mt][nt][3] * L2E);
        }
    }
}

// ---------------- tf32 GEMM, cp.async 3-stage, paired-W B operand ----------------
#define AST 40
#define BSTP 264
#define STAGE_A (128 * AST)
#define STAGE_B (16 * BSTP)
#define GSTAGE (STAGE_A + STAGE_B)
#define GEMM_SMEM (3 * GSTAGE * 4)

#define GEMM_CPA(stage, k0) do {                                              \
    unsigned as0 = sbase + (stage) * (GSTAGE * 4);                            \
    unsigned bs0 = as0 + STAGE_A * 4;                                         \
    _Pragma("unroll")                                                         \
    for (int p = 0; p < 4; p++) { int c = tid + 256 * p;                      \
        int r = c >> 3, q = (c & 7) * 4;                                      \
        cp16(as0 + (r * AST + q) * 4, &A[(size_t)(m0 + r) * Dn + (k0) + q]); }\
    _Pragma("unroll")                                                         \
    for (int p = 0; p < 4; p++) { int c = tid + 256 * p;                      \
        int k2 = c >> 6, nc = c & 63;                                         \
        cp16(bs0 + (k2 * BSTP + nc * 4) * 4,                                  \
             &W[(size_t)((k0) / 2 + k2) * 2048 + n0 * 2 + nc * 4]); }         \
    asm volatile("cp.async.commit_group;");                                   \
} while (0)

__global__ __launch_bounds__(256, 2) void gemm_tf32(
    const float* __restrict__ A,
    const float* __restrict__ W0, const float* __restrict__ W1, const float* __restrict__ W2,
    const float* __restrict__ c0p, const float* __restrict__ c1p, const float* __restrict__ c2p,
    float* __restrict__ C0, float* __restrict__ C1, float* __restrict__ C2,
    int roundC, int pairV)
{
    const float* __restrict__ W    = (blockIdx.z == 0) ? W0 : (blockIdx.z == 1) ? W1 : W2;
    const float* __restrict__ bias = (blockIdx.z == 0) ? c0p : (blockIdx.z == 1) ? c1p : c2p;
    float* __restrict__ C          = (blockIdx.z == 0) ? C0 : (blockIdx.z == 1) ? C1 : C2;
    int dopair = pairV && (blockIdx.z == 2);

    extern __shared__ unsigned gsm[];
    unsigned sbase = (unsigned)__cvta_generic_to_shared(gsm);

    int tid = threadIdx.x, lane = tid & 31, warp = tid >> 5;
    int g = lane >> 2, t = lane & 3;
    int wm = warp >> 2, wn = warp & 3;
    int m0 = blockIdx.y * 128, n0 = blockIdx.x * 128;

    float acc[4][4][4];
    #pragma unroll
    for (int i = 0; i < 4; i++)
        #pragma unroll
        for (int j = 0; j < 4; j++)
            #pragma unroll
            for (int r = 0; r < 4; r++) acc[i][j][r] = 0.0f;

    GEMM_CPA(0, 0);
    GEMM_CPA(1, 32);

    for (int it = 0; it < 32; ++it) {
        if (it < 31) asm volatile("cp.async.wait_group 1;");
        else         asm volatile("cp.async.wait_group 0;");
        __syncthreads();
        if (it < 30) {
            int nst = (it + 2) % 3;
            GEMM_CPA(nst, (it + 2) * 32);
        }
        unsigned* Asb = gsm + (it % 3) * GSTAGE;
        unsigned* Bsb = Asb + STAGE_A;
        #pragma unroll
        for (int s = 0; s < 4; ++s) {
            int kb = s * 8 + 2 * t;
            unsigned a[4][4];
            #pragma unroll
            for (int mt = 0; mt < 4; ++mt) {
                int r = (wm * 64 + mt * 16 + g) * AST + kb;
                uint2 lo = *(const uint2*)&Asb[r];
                uint2 hi = *(const uint2*)&Asb[r + 8 * AST];
                a[mt][0] = lo.x; a[mt][1] = hi.x; a[mt][2] = lo.y; a[mt][3] = hi.y;
            }
            #pragma unroll
            for (int nt = 0; nt < 4; ++nt) {
                int col = wn * 32 + nt * 8 + g;
                uint2 qq = *(const uint2*)&Bsb[(s * 4 + t) * BSTP + col * 2];
                #pragma unroll
                for (int mt = 0; mt < 4; ++mt)
                    mma8(acc[mt][nt], a[mt][0], a[mt][1], a[mt][2], a[mt][3], qq.x, qq.y);
            }
        }
    }

    #pragma unroll
    for (int mt = 0; mt < 4; ++mt) {
        int row = m0 + wm * 64 + mt * 16 + g;
        #pragma unroll
        for (int nt = 0; nt < 4; ++nt) {
            int col = n0 + wn * 32 + nt * 8 + 2 * t;
            float b0 = bias[col], b1 = bias[col + 1];
            float x0 = acc[mt][nt][0] + b0, x1 = acc[mt][nt][1] + b1;
            float x2 = acc[mt][nt][2] + b0, x3 = acc[mt][nt][3] + b1;
            if (roundC) {
                x0 = __uint_as_float(f2tf(x0)); x1 = __uint_as_float(f2tf(x1));
                x2 = __uint_as_float(f2tf(x2)); x3 = __uint_as_float(f2tf(x3));
            }
            if (dopair) {
                size_t ba0 = (size_t)(row >> 1) * 2048 + (row & 1);
                size_t ba1 = (size_t)((row + 8) >> 1) * 2048 + ((row + 8) & 1);
                C[ba0 + (size_t)col * 2]       = x0;
                C[ba0 + (size_t)(col + 1) * 2] = x1;
                C[ba1 + (size_t)col * 2]       = x2;
                C[ba1 + (size_t)(col + 1) * 2] = x3;
            } else {
                *(float2*)&C[(size_t)row * Dn + col]       = make_float2(x0, x1);
                *(float2*)&C[(size_t)(row + 8) * Dn + col] = make_float2(x2, x3);
            }
        }
    }
}

// ---------------- tf32 flash attention: no-max softmax, paired V, raw-fp32 P (truncation) ----------------
#define KST2 72
#define VSTP 136
#define BST2 40
#define KS2 (32 * KST2)
#define VS2 (16 * VSTP)
#define BS2 (64 * BST2)
#define KVB (KS2 + VS2 + BS2)
#define ATT_SMEM (2 * KVB * 4)             // 56320 B -> 4 CTAs/SM

#define ISSUE_KV(stage, kb) do {                                               \
    unsigned ks0 = abase + (stage) * (KVB * 4);                                \
    unsigned vs0 = ks0 + KS2 * 4;                                              \
    unsigned bs0 = vs0 + VS2 * 4;                                              \
    int r2b = (rowoff + (kb)) >> 1;                                            \
    _Pragma("unroll")                                                          \
    for (int p = 0; p < 4; p++) { int c = tid + 128 * p;                       \
        int r = c >> 4, d4 = (c & 15) * 4;                                     \
        cp16(ks0 + (r * KST2 + d4) * 4,                                        \
             &Kp[(size_t)(rowoff + (kb) + r) * Dn + h * DKn + d4]); }          \
    _Pragma("unroll")                                                          \
    for (int p = 0; p < 4; p++) { int c = tid + 128 * p;                       \
        int r2 = c >> 5, q = c & 31;                                           \
        cp16(vs0 + (r2 * VSTP + q * 4) * 4,                                    \
             &Vp[(size_t)(r2b + r2) * 2048 + h * 128 + q * 4]); }              \
    _Pragma("unroll")                                                          \
    for (int p = 0; p < 4; p++) { int c = tid + 128 * p;                       \
        int r = c >> 3, d4 = (c & 7) * 4;                                      \
        cp16(bs0 + (r * BST2 + d4) * 4,                                        \
             &Bbp[(size_t)(qbase + r) * Sn + (kb) + d4]); }                    \
    asm volatile("cp.async.commit_group;");                                    \
} while (0)

__global__ __launch_bounds__(128, 4) void attn_tf32(
    const float* __restrict__ Qp, const float* __restrict__ Kp, const float* __restrict__ Vp,
    const float* __restrict__ Biasp,
    float* __restrict__ O)
{
    extern __shared__ unsigned sm[];
    unsigned abase = (unsigned)__cvta_generic_to_shared(sm);

    int tid = threadIdx.x, lane = tid & 31, warp = tid >> 5;
    int g = lane >> 2, t = lane & 3;
    int qt = 31 - blockIdx.x;
    int h = blockIdx.y, b = blockIdx.z;
    int qbase = qt * 64, rowoff = b * Sn;
    int wq = warp * 16;
    const float* Bbp = Biasp + (size_t)b * Sn * Sn;

    const float L2E = 1.4426950408889634f;
    for (int i = tid; i < 64 * 16; i += 128) {
        int r = i >> 4, d4 = (i & 15) * 4;
        float4 v = *(const float4*)&Qp[(size_t)(rowoff + qbase + r) * Dn + h * DKn + d4];
        float sc = L2E * 0.125f;
        *(uint4*)&sm[r * KST2 + d4] =
            make_uint4(f2tf(v.x * sc), f2tf(v.y * sc), f2tf(v.z * sc), f2tf(v.w * sc));
    }
    __syncthreads();

    unsigned qreg[8][4];
    #pragma unroll
    for (int oct = 0; oct < 8; oct++) {
        int kk = oct * 8 + 2 * t;
        uint2 alo = *(const uint2*)&sm[(wq + g) * KST2 + kk];
        uint2 ahi = *(const uint2*)&sm[(wq + g + 8) * KST2 + kk];
        qreg[oct][0] = alo.x; qreg[oct][1] = ahi.x;
        qreg[oct][2] = alo.y; qreg[oct][3] = ahi.y;
    }
    __syncthreads();

    float o[8][4];
    #pragma unroll
    for (int vt = 0; vt < 8; vt++)
        #pragma unroll
        for (int j = 0; j < 4; j++) o[vt][j] = 0.0f;
    float l0 = 0.0f, l1 = 0.0f;

    int rg0 = qbase + wq + g, rg1 = rg0 + 8;
    int jmax = 2 * qt + 1;

    ISSUE_KV(0, 0);

    for (int jt = 0; jt <= jmax; jt++) {
        int cur = jt & 1;
        if (jt < jmax) {
            ISSUE_KV(cur ^ 1, (jt + 1) * 32);
            asm volatile("cp.async.wait_group 1;");
        } else {
            asm volatile("cp.async.wait_group 0;");
        }
        __syncthreads();

        unsigned* Ks = sm + cur * KVB;
        unsigned* Vs = Ks + KS2;
        const float* Bf = (const float*)(Vs + VS2);
        int kb = jt * 32;

        // ---- S = Q . K^T (k=64) ----
        float s[4][4];
        #pragma unroll
        for (int nt = 0; nt < 4; nt++)
            #pragma unroll
            for (int j = 0; j < 4; j++) s[nt][j] = 0.0f;

        #pragma unroll
        for (int oct = 0; oct < 8; oct++) {
            int kk = oct * 8 + 2 * t;
            #pragma unroll
            for (int nt = 0; nt < 4; nt++) {
                uint2 bb = *(const uint2*)&Ks[(nt * 8 + g) * KST2 + kk];
                mma8(s[nt], qreg[oct][0], qreg[oct][1], qreg[oct][2], qreg[oct][3],
                     bb.x, bb.y);
            }
        }

        // ---- + bias, causal mask ----
        #pragma unroll
        for (int nt = 0; nt < 4; nt++) {
            float2 b0v = *(const float2*)&Bf[(wq + g) * BST2 + nt * 8 + 2 * t];
            float2 b1v = *(const float2*)&Bf[(wq + g + 8) * BST2 + nt * 8 + 2 * t];
            s[nt][0] += b0v.x; s[nt][1] += b0v.y;
            s[nt][2] += b1v.x; s[nt][3] += b1v.y;
        }
        if (kb + 31 > rg0) {
            #pragma unroll
            for (int nt = 0; nt < 4; nt++) {
                int c0 = kb + nt * 8 + 2 * t, c1 = c0 + 1;
                if (c0 > rg0) s[nt][0] = -1e30f;
                if (c1 > rg0) s[nt][1] = -1e30f;
                if (c0 > rg1) s[nt][2] = -1e30f;
                if (c1 > rg1) s[nt][3] = -1e30f;
            }
        }

        // ---- p = ex2(s), accumulate l per-lane; P fed to mma as raw fp32 (tf32-truncated) ----
        #pragma unroll
        for (int nt = 0; nt < 4; nt++) {
            s[nt][0] = ex2(s[nt][0]);
            s[nt][1] = ex2(s[nt][1]);
            s[nt][2] = ex2(s[nt][2]);
            s[nt][3] = ex2(s[nt][3]);
            l0 += s[nt][0] + s[nt][1];
            l1 += s[nt][2] + s[nt][3];
        }

        #pragma unroll
        for (int oct = 0; oct < 4; oct++) {
            unsigned pa0 = __float_as_uint(s[oct][0]);
            unsigned pa1 = __float_as_uint(s[oct][2]);
            unsigned pa2 = __float_as_uint(s[oct][1]);
            unsigned pa3 = __float_as_uint(s[oct][3]);
            int r2row = oct * 4 + t;
            #pragma unroll
            for (int vt = 0; vt < 8; vt++) {
                uint2 bb = *(const uint2*)&Vs[r2row * VSTP + (vt * 8 + g) * 2];
                mma8(o[vt], pa0, pa1, pa2, pa3, bb.x, bb.y);
            }
        }
        __syncthreads();
    }

    // ---- epilogue: reduce l over the 4-lane t-group, normalize, store ----
    l0 += __shfl_xor_sync(0xffffffffu, l0, 1);
    l0 += __shfl_xor_sync(0xffffffffu, l0, 2);
    l1 += __shfl_xor_sync(0xffffffffu, l1, 1);
    l1 += __shfl_xor_sync(0xffffffffu, l1, 2);
    float inv0 = 1.0f / l0, inv1 = 1.0f / l1;
    int r0 = rowoff + rg0, r1 = rowoff + rg1;
    #pragma unroll
    for (int vt = 0; vt < 8; vt++) {
        int col = h * DKn + vt * 8 + 2 * t;
        *(uint2*)&O[(size_t)r0 * Dn + col] =
            make_uint2(f2tf(o[vt][0] * inv0), f2tf(o[vt][1] * inv0));
        *(uint2*)&O[(size_t)r1 * Dn + col] =
            make_uint2(f2tf(o[vt][2] * inv1), f2tf(o[vt][3] * inv1));
    }
}

// ---------------- launch ----------------
extern "C" void kernel_launch(void* const* d_in, const int* in_sizes, int n_in,
                              void* d_out, int out_size)
{
    const float* x    = (const float*)d_in[0];
    const float* feat = (const float*)d_in[1];
    const float* req  = (const float*)d_in[2];
    const float* Wq   = (const float*)d_in[3];
    const float* bq   = (const float*)d_in[4];
    const float* Wk   = (const float*)d_in[5];
    const float* bk   = (const float*)d_in[6];
    const float* Wv   = (const float*)d_in[7];
    const float* bv   = (const float*)d_in[8];
    const float* Wo   = (const float*)d_in[9];
    const float* bo   = (const float*)d_in[10];
    float* out = (float*)d_out;

    float *gQ, *gK, *gV, *gA, *gX, *gWp, *gB;
    cudaGetSymbolAddress((void**)&gQ,  g_Q);
    cudaGetSymbolAddress((void**)&gK,  g_K);
    cudaGetSymbolAddress((void**)&gV,  g_V);
    cudaGetSymbolAddress((void**)&gA,  g_A);
    cudaGetSymbolAddress((void**)&gX,  g_X);
    cudaGetSymbolAddress((void**)&gWp, g_Wp);
    cudaGetSymbolAddress((void**)&gB,  g_Bias);
    const float* gWpq = gWp;
    const float* gWpk = gWp + Dn * Dn;
    const float* gWpv = gWp + 2 * Dn * Dn;
    const float* gWpo = gWp + 3 * Dn * Dn;

    cudaFuncSetAttribute(gemm_tf32,
                         cudaFuncAttributeMaxDynamicSharedMemorySize, GEMM_SMEM);
    cudaFuncSetAttribute(attn_tf32,
                         cudaFuncAttributeMaxDynamicSharedMemorySize, ATT_SMEM);
    cudaFuncSetAttribute(bias_gemm,
                         cudaFuncAttributeMaxDynamicSharedMemorySize, BIAS_SMEM);

    round_inputs<<<8192, 256>>>(x, Wq, Wk, Wv, Wo);
    bias_gemm<<<dim3(16, 16, 2), 256, BIAS_SMEM>>>(req, feat, gB);

    gemm_tf32<<<dim3(8, 32, 3), 256, GEMM_SMEM>>>(
        gX, gWpq, gWpk, gWpv, bq, bk, bv, gQ, gK, gV, 1, 1);

    attn_tf32<<<dim3(32, Hn, Bn), 128, ATT_SMEM>>>(gQ, gK, gV, gB, gA);

    gemm_tf32<<<dim3(8, 32, 1), 256, GEMM_SMEM>>>(
        gA, gWpo, gWpo, gWpo, bo, bo, bo, out, out, out, 0, 0);
}

// round 15
// speedup vs baseline: 1.6587x; 1.5492x over previous
#include <cuda_runtime.h>
#include <cuda_fp16.h>
#include <math.h>

#define Bn 2
#define Sn 2048
#define Dn 1024
#define Hn 16
#define DKn 64
#define FDn 64
#define Mrows (Bn*Sn)

// ---------------- scratch ----------------
__device__ __half g_Xh[Mrows * Dn];          // x fp16
__device__ __half g_Wth[4][Dn * Dn];         // W^T [n][k] fp16
__device__ __half g_Qh[Mrows * Dn];          // Q * log2e/8, fp16
__device__ __half g_Kh[Mrows * Dn];          // K fp16
__device__ __half g_Vth[Dn * Mrows];         // V^T: [d][b*S+s] fp16
__device__ __half g_Ah[Mrows * Dn];          // attention out fp16
__device__ float  g_Bias[(size_t)Bn * Sn * Sn];  // req.feat^T * log2e (fp32)

__device__ __forceinline__ unsigned f2tf(float x) {
    unsigned r; asm("cvt.rna.tf32.f32 %0, %1;" : "=r"(r) : "f"(x)); return r;
}
__device__ __forceinline__ float ex2(float x) {
    float r; asm("ex2.approx.f32 %0, %1;" : "=f"(r) : "f"(x)); return r;
}
__device__ __forceinline__ unsigned h2pack(float lo, float hi) {
    unsigned r; asm("cvt.rn.f16x2.f32 %0, %1, %2;" : "=r"(r) : "f"(hi), "f"(lo)); return r;
}
// tf32 k8 mma (bias_gemm only)
__device__ __forceinline__ void mma8(float* c, unsigned a0, unsigned a1,
                                     unsigned a2, unsigned a3,
                                     unsigned b0, unsigned b1) {
    asm volatile("mma.sync.aligned.m16n8k8.row.col.f32.tf32.tf32.f32 "
                 "{%0,%1,%2,%3}, {%4,%5,%6,%7}, {%8,%9}, {%0,%1,%2,%3};"
                 : "+f"(c[0]), "+f"(c[1]), "+f"(c[2]), "+f"(c[3])
                 : "r"(a0), "r"(a1), "r"(a2), "r"(a3), "r"(b0), "r"(b1));
}
// fp16 k16 mma, fp32 accum
__device__ __forceinline__ void mma16(float* c, unsigned a0, unsigned a1,
                                      unsigned a2, unsigned a3,
                                      unsigned b0, unsigned b1) {
    asm volatile("mma.sync.aligned.m16n8k16.row.col.f32.f16.f16.f32 "
                 "{%0,%1,%2,%3}, {%4,%5,%6,%7}, {%8,%9}, {%0,%1,%2,%3};"
                 : "+f"(c[0]), "+f"(c[1]), "+f"(c[2]), "+f"(c[3])
                 : "r"(a0), "r"(a1), "r"(a2), "r"(a3), "r"(b0), "r"(b1));
}
__device__ __forceinline__ void cp16(unsigned dst, const void* src) {
    asm volatile("cp.async.cg.shared.global [%0], [%1], 16;" :: "r"(dst), "l"(src));
}

// ---------------- x -> fp16 ----------------
__global__ __launch_bounds__(256) void round_x(const float* __restrict__ x) {
    int idx = blockIdx.x * 256 + threadIdx.x;     // float4 index, 1048576 total
    float4 v = ((const float4*)x)[idx];
    ((uint2*)g_Xh)[idx] = make_uint2(h2pack(v.x, v.y), h2pack(v.z, v.w));
}

// ---------------- W -> W^T fp16 ----------------
__global__ __launch_bounds__(256) void transpose_w(
    const float* __restrict__ Wq, const float* __restrict__ Wk,
    const float* __restrict__ Wv, const float* __restrict__ Wo)
{
    __shared__ float ts[32][33];
    int w = blockIdx.z;
    const float* W = (w == 0) ? Wq : (w == 1) ? Wk : (w == 2) ? Wv : Wo;
    __half* Wt = g_Wth[w];
    int k0 = blockIdx.x * 32, n0 = blockIdx.y * 32;
    int j = threadIdx.x & 31, i = threadIdx.x >> 5;
    #pragma unroll
    for (int p = 0; p < 4; p++)
        ts[i + 8 * p][j] = W[(size_t)(k0 + i + 8 * p) * Dn + n0 + j];
    __syncthreads();
    #pragma unroll
    for (int p = 0; p < 4; p++)
        Wt[(size_t)(n0 + i + 8 * p) * Dn + k0 + j] = __float2half(ts[j][i + 8 * p]);
}

// ---------------- bias GEMM (fused l2norm, tf32) ----------------
#define FST 72
#define BIAS_SMEM (2 * 128 * FST * 4)
__global__ __launch_bounds__(256) void bias_gemm(
    const float* __restrict__ Rq, const float* __restrict__ Fq, float* __restrict__ Bias)
{
    if (blockIdx.x > blockIdx.y) return;
    extern __shared__ unsigned bsm[];
    unsigned* As = bsm;
    unsigned* Bs = bsm + 128 * FST;

    int tid = threadIdx.x, lane = tid & 31, warp = tid >> 5;
    int g = lane >> 2, t = lane & 3;
    int wm = warp >> 2, wn = warp & 3;
    int i0 = blockIdx.y * 128, j0 = blockIdx.x * 128, bz = blockIdx.z;
    const float* R = Rq + (size_t)bz * Sn * FDn;
    const float* F = Fq + (size_t)bz * Sn * FDn;

    for (int i = tid; i < 128 * 16; i += 256) {
        int r = i >> 4, d4 = (i & 15) * 4;
        *(float4*)((float*)&As[r * FST + d4]) = *(const float4*)&R[(size_t)(i0 + r) * FDn + d4];
        *(float4*)((float*)&Bs[r * FST + d4]) = *(const float4*)&F[(size_t)(j0 + r) * FDn + d4];
    }
    __syncthreads();

    {
        float* rowp = (tid < 128) ? (float*)&As[tid * FST] : (float*)&Bs[(tid - 128) * FST];
        float ss = 0.0f;
        #pragma unroll
        for (int i = 0; i < 16; i++) {
            float4 v = *(const float4*)&rowp[i * 4];
            ss += v.x * v.x + v.y * v.y + v.z * v.z + v.w * v.w;
        }
        float inv = 1.0f / fmaxf(sqrtf(ss), 1e-12f);
        #pragma unroll
        for (int i = 0; i < 16; i++) {
            float4 v = *(const float4*)&rowp[i * 4];
            *(uint4*)&rowp[i * 4] =
                make_uint4(f2tf(v.x * inv), f2tf(v.y * inv), f2tf(v.z * inv), f2tf(v.w * inv));
        }
    }
    __syncthreads();

    float acc[4][4][4];
    #pragma unroll
    for (int i = 0; i < 4; i++)
        #pragma unroll
        for (int j = 0; j < 4; j++)
            #pragma unroll
            for (int r = 0; r < 4; r++) acc[i][j][r] = 0.0f;

    #pragma unroll
    for (int oct = 0; oct < 8; oct++) {
        int kk = oct * 8 + 2 * t;
        #pragma unroll
        for (int mt = 0; mt < 4; mt++) {
            int r = (wm * 64 + mt * 16 + g) * FST + kk;
            uint2 lo = *(const uint2*)&As[r];
            uint2 hi = *(const uint2*)&As[r + 8 * FST];
            #pragma unroll
            for (int nt = 0; nt < 4; nt++) {
                uint2 bb = *(const uint2*)&Bs[(wn * 32 + nt * 8 + g) * FST + kk];
                mma8(acc[mt][nt], lo.x, hi.x, lo.y, hi.y, bb.x, bb.y);
            }
        }
    }

    const float L2E = 1.4426950408889634f;
    float* C = Bias + (size_t)bz * Sn * Sn;
    #pragma unroll
    for (int mt = 0; mt < 4; mt++) {
        int row = i0 + wm * 64 + mt * 16 + g;
        #pragma unroll
        for (int nt = 0; nt < 4; nt++) {
            int col = j0 + wn * 32 + nt * 8 + 2 * t;
            *(float2*)&C[(size_t)row * Sn + col] =
                make_float2(acc[mt][nt][0] * L2E, acc[mt][nt][1] * L2E);
            *(float2*)&C[(size_t)(row + 8) * Sn + col] =
                make_float2(acc[mt][nt][2] * L2E, acc[mt][nt][3] * L2E);
        }
    }
}

// ---------------- fp16 GEMM: C = A[4096,1024] . Wt[n][k]^T + bias ----------------
// 128x128 tile, k-step 32, 256 thr, 3-stage cp.async. emode: 0=f32 out, 1=f16 rowmajor*scale, 2=f16 V^T scatter.
#define GHS 40                              // halves per smem row (32+8)
#define GSTB 20480                          // bytes per stage (A 10240 + B 10240)
#define GEMM_SMEM (3 * GSTB)                // 61440

#define GF_CPA(stage, k0) do {                                                \
    unsigned a0_ = sbase + (stage) * GSTB;                                    \
    unsigned b0_ = a0_ + 10240;                                               \
    _Pragma("unroll")                                                         \
    for (int p = 0; p < 2; p++) { int c = tid + 256 * p;                      \
        int r = c >> 2, ch = c & 3;                                           \
        cp16(a0_ + r * 80 + ch * 16, &Ag[(size_t)(m0 + r) * Dn + (k0) + ch * 8]); } \
    _Pragma("unroll")                                                         \
    for (int p = 0; p < 2; p++) { int c = tid + 256 * p;                      \
        int r = c >> 2, ch = c & 3;                                           \
        cp16(b0_ + r * 80 + ch * 16, &Wt[(size_t)(n0 + r) * Dn + (k0) + ch * 8]); } \
    asm volatile("cp.async.commit_group;");                                   \
} while (0)

__global__ __launch_bounds__(256, 2) void gemm_f16(
    const __half* __restrict__ Ag,
    const __half* __restrict__ Wt0, const __half* __restrict__ Wt1, const __half* __restrict__ Wt2,
    const float* __restrict__ c0p, const float* __restrict__ c1p, const float* __restrict__ c2p,
    float* __restrict__ Cf,
    __half* __restrict__ Ch0, __half* __restrict__ Ch1, __half* __restrict__ Ch2,
    int qkv, float qscale)
{
    const __half* __restrict__ Wt  = (blockIdx.z == 0) ? Wt0 : (blockIdx.z == 1) ? Wt1 : Wt2;
    const float* __restrict__ bias = (blockIdx.z == 0) ? c0p : (blockIdx.z == 1) ? c1p : c2p;
    __half* __restrict__ Ch        = (blockIdx.z == 0) ? Ch0 : (blockIdx.z == 1) ? Ch1 : Ch2;
    int emode = qkv ? ((blockIdx.z == 2) ? 2 : 1) : 0;
    float scale = (qkv && blockIdx.z == 0) ? qscale : 1.0f;

    extern __shared__ char gsm[];
    unsigned sbase = (unsigned)__cvta_generic_to_shared(gsm);

    int tid = threadIdx.x, lane = tid & 31, warp = tid >> 5;
    int g = lane >> 2, t = lane & 3;
    int wm = warp >> 2, wn = warp & 3;
    int m0 = blockIdx.y * 128, n0 = blockIdx.x * 128;

    float acc[4][4][4];
    #pragma unroll
    for (int i = 0; i < 4; i++)
        #pragma unroll
        for (int j = 0; j < 4; j++)
            #pragma unroll
            for (int r = 0; r < 4; r++) acc[i][j][r] = 0.0f;

    GF_CPA(0, 0);
    GF_CPA(1, 32);

    for (int it = 0; it < 32; ++it) {
        if (it < 31) asm volatile("cp.async.wait_group 1;");
        else         asm volatile("cp.async.wait_group 0;");
        __syncthreads();
        if (it < 30) GF_CPA((it + 2) % 3, (it + 2) * 32);

        const __half* Ash = (const __half*)(gsm + (it % 3) * GSTB);
        const __half* Bsh = Ash + 5120;
        #pragma unroll
        for (int kc = 0; kc < 2; ++kc) {
            int kb = kc * 16 + 2 * t;
            unsigned a[4][4];
            #pragma unroll
            for (int mt = 0; mt < 4; ++mt) {
                int row = wm * 64 + mt * 16 + g;
                a[mt][0] = *(const unsigned*)&Ash[row * GHS + kb];
                a[mt][1] = *(const unsigned*)&Ash[(row + 8) * GHS + kb];
                a[mt][2] = *(const unsigned*)&Ash[row * GHS + kb + 8];
                a[mt][3] = *(const unsigned*)&Ash[(row + 8) * GHS + kb + 8];
            }
            #pragma unroll
            for (int nt = 0; nt < 4; ++nt) {
                int cn = wn * 32 + nt * 8 + g;
                unsigned b0 = *(const unsigned*)&Bsh[cn * GHS + kb];
                unsigned b1 = *(const unsigned*)&Bsh[cn * GHS + kb + 8];
                #pragma unroll
                for (int mt = 0; mt < 4; ++mt)
                    mma16(acc[mt][nt], a[mt][0], a[mt][1], a[mt][2], a[mt][3], b0, b1);
            }
        }
    }

    #pragma unroll
    for (int mt = 0; mt < 4; ++mt) {
        int row = m0 + wm * 64 + mt * 16 + g;
        #pragma unroll
        for (int nt = 0; nt < 4; ++nt) {
            int col = n0 + wn * 32 + nt * 8 + 2 * t;
            float b0 = bias[col], b1 = bias[col + 1];
            float x0 = acc[mt][nt][0] + b0, x1 = acc[mt][nt][1] + b1;
            float x2 = acc[mt][nt][2] + b0, x3 = acc[mt][nt][3] + b1;
            if (emode == 0) {
                *(float2*)&Cf[(size_t)row * Dn + col]       = make_float2(x0, x1);
                *(float2*)&Cf[(size_t)(row + 8) * Dn + col] = make_float2(x2, x3);
            } else if (emode == 1) {
                *(unsigned*)&Ch[(size_t)row * Dn + col]       = h2pack(x0 * scale, x1 * scale);
                *(unsigned*)&Ch[(size_t)(row + 8) * Dn + col] = h2pack(x2 * scale, x3 * scale);
            } else {    // V^T scatter: Ch[d][b*S+s]
                Ch[(size_t)col * Mrows + row]           = __float2half(x0);
                Ch[(size_t)(col + 1) * Mrows + row]     = __float2half(x1);
                Ch[(size_t)col * Mrows + row + 8]       = __float2half(x2);
                Ch[(size_t)(col + 1) * Mrows + row + 8] = __float2half(x3);
            }
        }
    }
}

// ---------------- fp16 flash attention: q64/128thr, no-max softmax ----------------
// Smem per stage: K [32][72h]=4608B, V^T [64][40h]=5120B, bias [64][40f]=10240B
#define KHS 72
#define VHS 40
#define BFS 40
#define KSB 4608
#define VSB 5120
#define BSB 10240
#define STGB (KSB + VSB + BSB)             // 19968 B
#define ATT_SMEM (2 * STGB)                // 39936 B -> 4 CTAs/SM

#define ISSUE_KV(stage, kb) do {                                               \
    unsigned ks0 = abase + (stage) * STGB;                                     \
    unsigned vs0 = ks0 + KSB;                                                  \
    unsigned bs0 = vs0 + VSB;                                                  \
    _Pragma("unroll")                                                          \
    for (int p = 0; p < 2; p++) { int c = tid + 128 * p;                       \
        int r = c >> 3, ch = c & 7;                                            \
        cp16(ks0 + r * 144 + ch * 16,                                          \
             &Kh[(size_t)(rowoff + (kb) + r) * Dn + h * DKn + ch * 8]); }      \
    _Pragma("unroll")                                                          \
    for (int p = 0; p < 2; p++) { int c = tid + 128 * p;                       \
        int r = c >> 2, ch = c & 3;                                            \
        cp16(vs0 + r * 80 + ch * 16,                                           \
             &Vth[(size_t)(h * DKn + r) * Mrows + rowoff + (kb) + ch * 8]); }  \
    _Pragma("unroll")                                                          \
    for (int p = 0; p < 4; p++) { int c = tid + 128 * p;                       \
        int r = c >> 3, d4 = (c & 7) * 4;                                      \
        cp16(bs0 + r * 160 + d4 * 4,                                           \
             &Bbp[(size_t)(qbase + r) * Sn + (kb) + d4]); }                    \
    asm volatile("cp.async.commit_group;");                                    \
} while (0)

__global__ __launch_bounds__(128, 4) void attn_f16(
    const __half* __restrict__ Qh, const __half* __restrict__ Kh,
    const __half* __restrict__ Vth, const float* __restrict__ Biasp,
    __half* __restrict__ Ah)
{
    extern __shared__ char asmem[];
    unsigned abase = (unsigned)__cvta_generic_to_shared(asmem);
    __half* hsm = (__half*)asmem;

    int tid = threadIdx.x, lane = tid & 31, warp = tid >> 5;
    int g = lane >> 2, t = lane & 3;
    int qt = 31 - blockIdx.x;
    int h = blockIdx.y, b = blockIdx.z;
    int qbase = qt * 64, rowoff = b * Sn;
    int wq = warp * 16;
    const float* Bbp = Biasp + (size_t)b * Sn * Sn;

    // ---- stage Q tile [64][72h] via cp.async (Q already scaled), lift to regs ----
    #pragma unroll
    for (int p = 0; p < 4; p++) {
        int c = tid + 128 * p;
        int r = c >> 3, ch = c & 7;
        cp16(abase + r * 144 + ch * 16,
             &Qh[(size_t)(rowoff + qbase + r) * Dn + h * DKn + ch * 8]);
    }
    asm volatile("cp.async.commit_group;");
    asm volatile("cp.async.wait_group 0;");
    __syncthreads();

    unsigned qreg[4][4];
    #pragma unroll
    for (int o = 0; o < 4; o++) {
        int kb = o * 16 + 2 * t;
        qreg[o][0] = *(const unsigned*)&hsm[(wq + g) * KHS + kb];
        qreg[o][1] = *(const unsigned*)&hsm[(wq + g + 8) * KHS + kb];
        qreg[o][2] = *(const unsigned*)&hsm[(wq + g) * KHS + kb + 8];
        qreg[o][3] = *(const unsigned*)&hsm[(wq + g + 8) * KHS + kb + 8];
    }
    __syncthreads();

    float o[8][4];
    #pragma unroll
    for (int vt = 0; vt < 8; vt++)
        #pragma unroll
        for (int j = 0; j < 4; j++) o[vt][j] = 0.0f;
    float l0 = 0.0f, l1 = 0.0f;

    int rg0 = qbase + wq + g, rg1 = rg0 + 8;
    int jmax = 2 * qt + 1;

    ISSUE_KV(0, 0);

    for (int jt = 0; jt <= jmax; jt++) {
        int cur = jt & 1;
        if (jt < jmax) {
            ISSUE_KV(cur ^ 1, (jt + 1) * 32);
            asm volatile("cp.async.wait_group 1;");
        } else {
            asm volatile("cp.async.wait_group 0;");
        }
        __syncthreads();

        const __half* Ksh = (const __half*)(asmem + cur * STGB);
        const __half* Vsh = (const __half*)(asmem + cur * STGB + KSB);
        const float*  Bf  = (const float*)(asmem + cur * STGB + KSB + VSB);
        int kb = jt * 32;

        // ---- S = Q . K^T (k=64, 4 k16-steps) ----
        float s[4][4];
        #pragma unroll
        for (int nt = 0; nt < 4; nt++)
            #pragma unroll
            for (int j = 0; j < 4; j++) s[nt][j] = 0.0f;

        #pragma unroll
        for (int oc = 0; oc < 4; oc++) {
            int kk = oc * 16 + 2 * t;
            #pragma unroll
            for (int nt = 0; nt < 4; nt++) {
                int kr = nt * 8 + g;
                unsigned b0 = *(const unsigned*)&Ksh[kr * KHS + kk];
                unsigned b1 = *(const unsigned*)&Ksh[kr * KHS + kk + 8];
                mma16(s[nt], qreg[oc][0], qreg[oc][1], qreg[oc][2], qreg[oc][3], b0, b1);
            }
        }

        // ---- + bias, causal mask ----
        #pragma unroll
        for (int nt = 0; nt < 4; nt++) {
            float2 b0v = *(const float2*)&Bf[(wq + g) * BFS + nt * 8 + 2 * t];
            float2 b1v = *(const float2*)&Bf[(wq + g + 8) * BFS + nt * 8 + 2 * t];
            s[nt][0] += b0v.x; s[nt][1] += b0v.y;
            s[nt][2] += b1v.x; s[nt][3] += b1v.y;
        }
        if (kb + 31 > rg0) {
            #pragma unroll
            for (int nt = 0; nt < 4; nt++) {
                int c0 = kb + nt * 8 + 2 * t, c1 = c0 + 1;
                if (c0 > rg0) s[nt][0] = -1e30f;
                if (c1 > rg0) s[nt][1] = -1e30f;
                if (c0 > rg1) s[nt][2] = -1e30f;
                if (c1 > rg1) s[nt][3] = -1e30f;
            }
        }

        // ---- p = ex2(s), accumulate l; pack P to f16x2; O += P.V ----
        #pragma unroll
        for (int nt = 0; nt < 4; nt++) {
            s[nt][0] = ex2(s[nt][0]);
            s[nt][1] = ex2(s[nt][1]);
            s[nt][2] = ex2(s[nt][2]);
            s[nt][3] = ex2(s[nt][3]);
            l0 += s[nt][0] + s[nt][1];
            l1 += s[nt][2] + s[nt][3];
        }

        #pragma unroll
        for (int oc = 0; oc < 2; oc++) {      // kv16 chunks
            unsigned pa0 = h2pack(s[2*oc][0],     s[2*oc][1]);
            unsigned pa1 = h2pack(s[2*oc][2],     s[2*oc][3]);
            unsigned pa2 = h2pack(s[2*oc + 1][0], s[2*oc + 1][1]);
            unsigned pa3 = h2pack(s[2*oc + 1][2], s[2*oc + 1][3]);
            int kk = oc * 16 + 2 * t;
            #pragma unroll
            for (int vt = 0; vt < 8; vt++) {
                int dr = vt * 8 + g;
                unsigned b0 = *(const unsigned*)&Vsh[dr * VHS + kk];
                unsigned b1 = *(const unsigned*)&Vsh[dr * VHS + kk + 8];
                mma16(o[vt], pa0, pa1, pa2, pa3, b0, b1);
            }
        }
        __syncthreads();
    }

    // ---- epilogue ----
    l0 += __shfl_xor_sync(0xffffffffu, l0, 1);
    l0 += __shfl_xor_sync(0xffffffffu, l0, 2);
    l1 += __shfl_xor_sync(0xffffffffu, l1, 1);
    l1 += __shfl_xor_sync(0xffffffffu, l1, 2);
    float inv0 = 1.0f / l0, inv1 = 1.0f / l1;
    int r0 = rowoff + rg0, r1 = rowoff + rg1;
    #pragma unroll
    for (int vt = 0; vt < 8; vt++) {
        int col = h * DKn + vt * 8 + 2 * t;
        *(unsigned*)&Ah[(size_t)r0 * Dn + col] = h2pack(o[vt][0] * inv0, o[vt][1] * inv0);
        *(unsigned*)&Ah[(size_t)r1 * Dn + col] = h2pack(o[vt][2] * inv1, o[vt][3] * inv1);
    }
}

// ---------------- launch ----------------
extern "C" void kernel_launch(void* const* d_in, const int* in_sizes, int n_in,
                              void* d_out, int out_size)
{
    const float* x    = (const float*)d_in[0];
    const float* feat = (const float*)d_in[1];
    const float* req  = (const float*)d_in[2];
    const float* Wq   = (const float*)d_in[3];
    const float* bq   = (const float*)d_in[4];
    const float* Wk   = (const float*)d_in[5];
    const float* bk   = (const float*)d_in[6];
    const float* Wv   = (const float*)d_in[7];
    const float* bv   = (const float*)d_in[8];
    const float* Wo   = (const float*)d_in[9];
    const float* bo   = (const float*)d_in[10];
    float* out = (float*)d_out;

    __half *gXh, *gWth, *gQh, *gKh, *gVth, *gAh;
    float *gB;
    cudaGetSymbolAddress((void**)&gXh,  g_Xh);
    cudaGetSymbolAddress((void**)&gWth, g_Wth);
    cudaGetSymbolAddress((void**)&gQh,  g_Qh);
    cudaGetSymbolAddress((void**)&gKh,  g_Kh);
    cudaGetSymbolAddress((void**)&gVth, g_Vth);
    cudaGetSymbolAddress((void**)&gAh,  g_Ah);
    cudaGetSymbolAddress((void**)&gB,   g_Bias);
    const __half* gWtq = gWth;
    const __half* gWtk = gWth + Dn * Dn;
    const __half* gWtv = gWth + 2 * Dn * Dn;
    const __half* gWto = gWth + 3 * Dn * Dn;

    cudaFuncSetAttribute(gemm_f16,
                         cudaFuncAttributeMaxDynamicSharedMemorySize, GEMM_SMEM);
    cudaFuncSetAttribute(attn_f16,
                         cudaFuncAttributeMaxDynamicSharedMemorySize, ATT_SMEM);
    cudaFuncSetAttribute(bias_gemm,
                         cudaFuncAttributeMaxDynamicSharedMemorySize, BIAS_SMEM);

    const float QS = 1.4426950408889634f * 0.125f;   // log2e / 8

    round_x<<<4096, 256>>>(x);
    transpose_w<<<dim3(32, 32, 4), 256>>>(Wq, Wk, Wv, Wo);
    bias_gemm<<<dim3(16, 16, 2), 256, BIAS_SMEM>>>(req, feat, gB);

    // QKV: z0 -> Q (f16, *QS), z1 -> K (f16), z2 -> V^T (f16 scatter)
    gemm_f16<<<dim3(8, 32, 3), 256, GEMM_SMEM>>>(
        gXh, gWtq, gWtk, gWtv, bq, bk, bv,
        (float*)nullptr, gQh, gKh, gVth, 1, QS);

    attn_f16<<<dim3(32, Hn, Bn), 128, ATT_SMEM>>>(gQh, gKh, gVth, gB, gAh);

    // output projection -> fp32 d_out
    gemm_f16<<<dim3(8, 32, 1), 256, GEMM_SMEM>>>(
        gAh, gWto, gWto, gWto, bo, bo, bo,
        out, (half*)nullptr, (half*)nullptr, (half*)nullptr, 0, 1.0f);
}

// round 16
// speedup vs baseline: 1.8371x; 1.1075x over previous
#include <cuda_runtime.h>
#include <cuda_fp16.h>
#include <math.h>

#define Bn 2
#define Sn 2048
#define Dn 1024
#define Hn 16
#define DKn 64
#define FDn 64
#define Mrows (Bn*Sn)

// ---------------- scratch ----------------
__device__ __half g_Xh[Mrows * Dn];
__device__ __half g_Wth[4][Dn * Dn];         // W^T [n][k] fp16
__device__ __half g_Qh[Mrows * Dn];          // Q * log2e/8
__device__ __half g_Kh[Mrows * Dn];
__device__ __half g_Vth[Dn * Mrows];         // V^T: [d][b*S+s]
__device__ __half g_Ah[Mrows * Dn];
__device__ float  g_Bias[(size_t)Bn * Sn * Sn];

__device__ __forceinline__ unsigned f2tf(float x) {
    unsigned r; asm("cvt.rna.tf32.f32 %0, %1;" : "=r"(r) : "f"(x)); return r;
}
__device__ __forceinline__ float ex2(float x) {
    float r; asm("ex2.approx.f32 %0, %1;" : "=f"(r) : "f"(x)); return r;
}
__device__ __forceinline__ unsigned h2pack(float lo, float hi) {
    unsigned r; asm("cvt.rn.f16x2.f32 %0, %1, %2;" : "=r"(r) : "f"(hi), "f"(lo)); return r;
}
__device__ __forceinline__ void mma8(float* c, unsigned a0, unsigned a1,
                                     unsigned a2, unsigned a3,
                                     unsigned b0, unsigned b1) {
    asm volatile("mma.sync.aligned.m16n8k8.row.col.f32.tf32.tf32.f32 "
                 "{%0,%1,%2,%3}, {%4,%5,%6,%7}, {%8,%9}, {%0,%1,%2,%3};"
                 : "+f"(c[0]), "+f"(c[1]), "+f"(c[2]), "+f"(c[3])
                 : "r"(a0), "r"(a1), "r"(a2), "r"(a3), "r"(b0), "r"(b1));
}
__device__ __forceinline__ void mma16(float* c, unsigned a0, unsigned a1,
                                      unsigned a2, unsigned a3,
                                      unsigned b0, unsigned b1) {
    asm volatile("mma.sync.aligned.m16n8k16.row.col.f32.f16.f16.f32 "
                 "{%0,%1,%2,%3}, {%4,%5,%6,%7}, {%8,%9}, {%0,%1,%2,%3};"
                 : "+f"(c[0]), "+f"(c[1]), "+f"(c[2]), "+f"(c[3])
                 : "r"(a0), "r"(a1), "r"(a2), "r"(a3), "r"(b0), "r"(b1));
}
__device__ __forceinline__ void ldsm4(unsigned& r0, unsigned& r1,
                                      unsigned& r2, unsigned& r3, unsigned addr) {
    asm volatile("ldmatrix.sync.aligned.m8n8.x4.shared.b16 {%0,%1,%2,%3}, [%4];"
                 : "=r"(r0), "=r"(r1), "=r"(r2), "=r"(r3) : "r"(addr));
}
__device__ __forceinline__ void cp16(unsigned dst, const void* src) {
    asm volatile("cp.async.cg.shared.global [%0], [%1], 16;" :: "r"(dst), "l"(src));
}

// ---------------- x -> fp16 ----------------
__global__ __launch_bounds__(256) void round_x(const float* __restrict__ x) {
    int idx = blockIdx.x * 256 + threadIdx.x;
    float4 v = ((const float4*)x)[idx];
    ((uint2*)g_Xh)[idx] = make_uint2(h2pack(v.x, v.y), h2pack(v.z, v.w));
}

// ---------------- W -> W^T fp16 ----------------
__global__ __launch_bounds__(256) void transpose_w(
    const float* __restrict__ Wq, const float* __restrict__ Wk,
    const float* __restrict__ Wv, const float* __restrict__ Wo)
{
    __shared__ float ts[32][33];
    int w = blockIdx.z;
    const float* W = (w == 0) ? Wq : (w == 1) ? Wk : (w == 2) ? Wv : Wo;
    __half* Wt = g_Wth[w];
    int k0 = blockIdx.x * 32, n0 = blockIdx.y * 32;
    int j = threadIdx.x & 31, i = threadIdx.x >> 5;
    #pragma unroll
    for (int p = 0; p < 4; p++)
        ts[i + 8 * p][j] = W[(size_t)(k0 + i + 8 * p) * Dn + n0 + j];
    __syncthreads();
    #pragma unroll
    for (int p = 0; p < 4; p++)
        Wt[(size_t)(n0 + i + 8 * p) * Dn + k0 + j] = __float2half(ts[j][i + 8 * p]);
}

// ---------------- bias GEMM (fused l2norm, tf32) ----------------
#define FST 72
#define BIAS_SMEM (2 * 128 * FST * 4)
__global__ __launch_bounds__(256) void bias_gemm(
    const float* __restrict__ Rq, const float* __restrict__ Fq, float* __restrict__ Bias)
{
    if (blockIdx.x > blockIdx.y) return;
    extern __shared__ unsigned bsm[];
    unsigned* As = bsm;
    unsigned* Bs = bsm + 128 * FST;

    int tid = threadIdx.x, lane = tid & 31, warp = tid >> 5;
    int g = lane >> 2, t = lane & 3;
    int wm = warp >> 2, wn = warp & 3;
    int i0 = blockIdx.y * 128, j0 = blockIdx.x * 128, bz = blockIdx.z;
    const float* R = Rq + (size_t)bz * Sn * FDn;
    const float* F = Fq + (size_t)bz * Sn * FDn;

    for (int i = tid; i < 128 * 16; i += 256) {
        int r = i >> 4, d4 = (i & 15) * 4;
        *(float4*)((float*)&As[r * FST + d4]) = *(const float4*)&R[(size_t)(i0 + r) * FDn + d4];
        *(float4*)((float*)&Bs[r * FST + d4]) = *(const float4*)&F[(size_t)(j0 + r) * FDn + d4];
    }
    __syncthreads();

    {
        float* rowp = (tid < 128) ? (float*)&As[tid * FST] : (float*)&Bs[(tid - 128) * FST];
        float ss = 0.0f;
        #pragma unroll
        for (int i = 0; i < 16; i++) {
            float4 v = *(const float4*)&rowp[i * 4];
            ss += v.x * v.x + v.y * v.y + v.z * v.z + v.w * v.w;
        }
        float inv = 1.0f / fmaxf(sqrtf(ss), 1e-12f);
        #pragma unroll
        for (int i = 0; i < 16; i++) {
            float4 v = *(const float4*)&rowp[i * 4];
            *(uint4*)&rowp[i * 4] =
                make_uint4(f2tf(v.x * inv), f2tf(v.y * inv), f2tf(v.z * inv), f2tf(v.w * inv));
        }
    }
    __syncthreads();

    float acc[4][4][4];
    #pragma unroll
    for (int i = 0; i < 4; i++)
        #pragma unroll
        for (int j = 0; j < 4; j++)
            #pragma unroll
            for (int r = 0; r < 4; r++) acc[i][j][r] = 0.0f;

    #pragma unroll
    for (int oct = 0; oct < 8; oct++) {
        int kk = oct * 8 + 2 * t;
        #pragma unroll
        for (int mt = 0; mt < 4; mt++) {
            int r = (wm * 64 + mt * 16 + g) * FST + kk;
            uint2 lo = *(const uint2*)&As[r];
            uint2 hi = *(const uint2*)&As[r + 8 * FST];
            #pragma unroll
            for (int nt = 0; nt < 4; nt++) {
                uint2 bb = *(const uint2*)&Bs[(wn * 32 + nt * 8 + g) * FST + kk];
                mma8(acc[mt][nt], lo.x, hi.x, lo.y, hi.y, bb.x, bb.y);
            }
        }
    }

    const float L2E = 1.4426950408889634f;
    float* C = Bias + (size_t)bz * Sn * Sn;
    #pragma unroll
    for (int mt = 0; mt < 4; mt++) {
        int row = i0 + wm * 64 + mt * 16 + g;
        #pragma unroll
        for (int nt = 0; nt < 4; nt++) {
            int col = j0 + wn * 32 + nt * 8 + 2 * t;
            *(float2*)&C[(size_t)row * Sn + col] =
                make_float2(acc[mt][nt][0] * L2E, acc[mt][nt][1] * L2E);
            *(float2*)&C[(size_t)(row + 8) * Sn + col] =
                make_float2(acc[mt][nt][2] * L2E, acc[mt][nt][3] * L2E);
        }
    }
}

// ---------------- fp16 GEMM with ldmatrix fragments ----------------
#define GHS 40
#define GSTB 20480
#define GEMM_SMEM (3 * GSTB)

#define GF_CPA(stage, k0) do {                                                \
    unsigned a0_ = sbase + (stage) * GSTB;                                    \
    unsigned b0_ = a0_ + 10240;                                               \
    _Pragma("unroll")                                                         \
    for (int p = 0; p < 2; p++) { int c = tid + 256 * p;                      \
        int r = c >> 2, ch = c & 3;                                           \
        cp16(a0_ + r * 80 + ch * 16, &Ag[(size_t)(m0 + r) * Dn + (k0) + ch * 8]); } \
    _Pragma("unroll")                                                         \
    for (int p = 0; p < 2; p++) { int c = tid + 256 * p;                      \
        int r = c >> 2, ch = c & 3;                                           \
        cp16(b0_ + r * 80 + ch * 16, &Wt[(size_t)(n0 + r) * Dn + (k0) + ch * 8]); } \
    asm volatile("cp.async.commit_group;");                                   \
} while (0)

__global__ __launch_bounds__(256, 2) void gemm_f16(
    const __half* __restrict__ Ag,
    const __half* __restrict__ Wt0, const __half* __restrict__ Wt1, const __half* __restrict__ Wt2,
    const float* __restrict__ c0p, const float* __restrict__ c1p, const float* __restrict__ c2p,
    float* __restrict__ Cf,
    __half* __restrict__ Ch0, __half* __restrict__ Ch1, __half* __restrict__ Ch2,
    int qkv, float qscale)
{
    const __half* __restrict__ Wt  = (blockIdx.z == 0) ? Wt0 : (blockIdx.z == 1) ? Wt1 : Wt2;
    const float* __restrict__ bias = (blockIdx.z == 0) ? c0p : (blockIdx.z == 1) ? c1p : c2p;
    __half* __restrict__ Ch        = (blockIdx.z == 0) ? Ch0 : (blockIdx.z == 1) ? Ch1 : Ch2;
    int emode = qkv ? ((blockIdx.z == 2) ? 2 : 1) : 0;
    float scale = (qkv && blockIdx.z == 0) ? qscale : 1.0f;

    extern __shared__ char gsm[];
    unsigned sbase = (unsigned)__cvta_generic_to_shared(gsm);

    int tid = threadIdx.x, lane = tid & 31, warp = tid >> 5;
    int g = lane >> 2, t = lane & 3;
    int l8 = lane & 7, quad = lane >> 3;
    int wm = warp >> 2, wn = warp & 3;
    int m0 = blockIdx.y * 128, n0 = blockIdx.x * 128;

    // ldmatrix per-lane row/col offsets (elements)
    int aRow = (quad & 1) * 8 + l8, aCol = (quad >> 1) * 8;   // A-frag mapping
    int bRow = (quad >> 1) * 8 + l8, bCol = (quad & 1) * 8;   // B-frag mapping

    float acc[4][4][4];
    #pragma unroll
    for (int i = 0; i < 4; i++)
        #pragma unroll
        for (int j = 0; j < 4; j++)
            #pragma unroll
            for (int r = 0; r < 4; r++) acc[i][j][r] = 0.0f;

    GF_CPA(0, 0);
    GF_CPA(1, 32);

    for (int it = 0; it < 32; ++it) {
        if (it < 31) asm volatile("cp.async.wait_group 1;");
        else         asm volatile("cp.async.wait_group 0;");
        __syncthreads();
        if (it < 30) GF_CPA((it + 2) % 3, (it + 2) * 32);

        unsigned sA = sbase + (it % 3) * GSTB;
        unsigned sB = sA + 10240;
        #pragma unroll
        for (int kc = 0; kc < 2; ++kc) {
            unsigned a[4][4], bfr[4][2];
            #pragma unroll
            for (int mt = 0; mt < 4; ++mt)
                ldsm4(a[mt][0], a[mt][1], a[mt][2], a[mt][3],
                      sA + ((wm * 64 + mt * 16 + aRow) * GHS + kc * 16 + aCol) * 2);
            #pragma unroll
            for (int p = 0; p < 2; ++p)
                ldsm4(bfr[2 * p][0], bfr[2 * p][1], bfr[2 * p + 1][0], bfr[2 * p + 1][1],
                      sB + ((wn * 32 + p * 16 + bRow) * GHS + kc * 16 + bCol) * 2);
            #pragma unroll
            for (int nt = 0; nt < 4; ++nt)
                #pragma unroll
                for (int mt = 0; mt < 4; ++mt)
                    mma16(acc[mt][nt], a[mt][0], a[mt][1], a[mt][2], a[mt][3],
                          bfr[nt][0], bfr[nt][1]);
        }
    }

    #pragma unroll
    for (int mt = 0; mt < 4; ++mt) {
        int row = m0 + wm * 64 + mt * 16 + g;
        #pragma unroll
        for (int nt = 0; nt < 4; ++nt) {
            int col = n0 + wn * 32 + nt * 8 + 2 * t;
            float b0 = bias[col], b1 = bias[col + 1];
            float x0 = acc[mt][nt][0] + b0, x1 = acc[mt][nt][1] + b1;
            float x2 = acc[mt][nt][2] + b0, x3 = acc[mt][nt][3] + b1;
            if (emode == 0) {
                *(float2*)&Cf[(size_t)row * Dn + col]       = make_float2(x0, x1);
                *(float2*)&Cf[(size_t)(row + 8) * Dn + col] = make_float2(x2, x3);
            } else if (emode == 1) {
                *(unsigned*)&Ch[(size_t)row * Dn + col]       = h2pack(x0 * scale, x1 * scale);
                *(unsigned*)&Ch[(size_t)(row + 8) * Dn + col] = h2pack(x2 * scale, x3 * scale);
            } else {
                Ch[(size_t)col * Mrows + row]           = __float2half(x0);
                Ch[(size_t)(col + 1) * Mrows + row]     = __float2half(x1);
                Ch[(size_t)col * Mrows + row + 8]       = __float2half(x2);
                Ch[(size_t)(col + 1) * Mrows + row + 8] = __float2half(x3);
            }
        }
    }
}

// ---------------- fp16 flash attention with ldmatrix fragments ----------------
#define KHS 72
#define VHS 40
#define BFS 40
#define KSB 4608
#define VSB 5120
#define BSB 10240
#define STGB (KSB + VSB + BSB)
#define ATT_SMEM (2 * STGB)

#define ISSUE_KV(stage, kb) do {                                               \
    unsigned ks0 = abase + (stage) * STGB;                                     \
    unsigned vs0 = ks0 + KSB;                                                  \
    unsigned bs0 = vs0 + VSB;                                                  \
    _Pragma("unroll")                                                          \
    for (int p = 0; p < 2; p++) { int c = tid + 128 * p;                       \
        int r = c >> 3, ch = c & 7;                                            \
        cp16(ks0 + r * 144 + ch * 16,                                          \
             &Kh[(size_t)(rowoff + (kb) + r) * Dn + h * DKn + ch * 8]); }      \
    _Pragma("unroll")                                                          \
    for (int p = 0; p < 2; p++) { int c = tid + 128 * p;                       \
        int r = c >> 2, ch = c & 3;                                            \
        cp16(vs0 + r * 80 + ch * 16,                                           \
             &Vth[(size_t)(h * DKn + r) * Mrows + rowoff + (kb) + ch * 8]); }  \
    _Pragma("unroll")                                                          \
    for (int p = 0; p < 4; p++) { int c = tid + 128 * p;                       \
        int r = c >> 3, d4 = (c & 7) * 4;                                      \
        cp16(bs0 + r * 160 + d4 * 4,                                           \
             &Bbp[(size_t)(qbase + r) * Sn + (kb) + d4]); }                    \
    asm volatile("cp.async.commit_group;");                                    \
} while (0)

__global__ __launch_bounds__(128, 4) void attn_f16(
    const __half* __restrict__ Qh, const __half* __restrict__ Kh,
    const __half* __restrict__ Vth, const float* __restrict__ Biasp,
    __half* __restrict__ Ah)
{
    extern __shared__ char asmem[];
    unsigned abase = (unsigned)__cvta_generic_to_shared(asmem);

    int tid = threadIdx.x, lane = tid & 31, warp = tid >> 5;
    int g = lane >> 2, t = lane & 3;
    int l8 = lane & 7, quad = lane >> 3;
    int qt = 31 - blockIdx.x;
    int h = blockIdx.y, b = blockIdx.z;
    int qbase = qt * 64, rowoff = b * Sn;
    int wq = warp * 16;
    const float* Bbp = Biasp + (size_t)b * Sn * Sn;

    int aRow = (quad & 1) * 8 + l8, aCol = (quad >> 1) * 8;
    int bRow = (quad >> 1) * 8 + l8, bCol = (quad & 1) * 8;

    // ---- stage Q tile [64][72h] via cp.async, lift to regs (ldmatrix) ----
    #pragma unroll
    for (int p = 0; p < 4; p++) {
        int c = tid + 128 * p;
        int r = c >> 3, ch = c & 7;
        cp16(abase + r * 144 + ch * 16,
             &Qh[(size_t)(rowoff + qbase + r) * Dn + h * DKn + ch * 8]);
    }
    asm volatile("cp.async.commit_group;");
    asm volatile("cp.async.wait_group 0;");
    __syncthreads();

    unsigned qreg[4][4];
    #pragma unroll
    for (int o = 0; o < 4; o++)
        ldsm4(qreg[o][0], qreg[o][1], qreg[o][2], qreg[o][3],
              abase + ((wq + aRow) * KHS + o * 16 + aCol) * 2);
    __syncthreads();

    float o[8][4];
    #pragma unroll
    for (int vt = 0; vt < 8; vt++)
        #pragma unroll
        for (int j = 0; j < 4; j++) o[vt][j] = 0.0f;
    float l0 = 0.0f, l1 = 0.0f;

    int rg0 = qbase + wq + g, rg1 = rg0 + 8;
    int jmax = 2 * qt + 1;

    ISSUE_KV(0, 0);

    for (int jt = 0; jt <= jmax; jt++) {
        int cur = jt & 1;
        if (jt < jmax) {
            ISSUE_KV(cur ^ 1, (jt + 1) * 32);
            asm volatile("cp.async.wait_group 1;");
        } else {
            asm volatile("cp.async.wait_group 0;");
        }
        __syncthreads();

        unsigned ksh = abase + cur * STGB;
        unsigned vsh = ksh + KSB;
        const float* Bf = (const float*)(asmem + cur * STGB + KSB + VSB);
        int kb = jt * 32;

        // ---- S = Q . K^T ----
        float s[4][4];
        #pragma unroll
        for (int nt = 0; nt < 4; nt++)
            #pragma unroll
            for (int j = 0; j < 4; j++) s[nt][j] = 0.0f;

        #pragma unroll
        for (int oc = 0; oc < 4; oc++) {
            unsigned kf[4][2];
            #pragma unroll
            for (int p = 0; p < 2; p++)
                ldsm4(kf[2 * p][0], kf[2 * p][1], kf[2 * p + 1][0], kf[2 * p + 1][1],
                      ksh + ((p * 16 + bRow) * KHS + oc * 16 + bCol) * 2);
            #pragma unroll
            for (int nt = 0; nt < 4; nt++)
                mma16(s[nt], qreg[oc][0], qreg[oc][1], qreg[oc][2], qreg[oc][3],
                      kf[nt][0], kf[nt][1]);
        }

        // ---- + bias, causal mask ----
        #pragma unroll
        for (int nt = 0; nt < 4; nt++) {
            float2 b0v = *(const float2*)&Bf[(wq + g) * BFS + nt * 8 + 2 * t];
            float2 b1v = *(const float2*)&Bf[(wq + g + 8) * BFS + nt * 8 + 2 * t];
            s[nt][0] += b0v.x; s[nt][1] += b0v.y;
            s[nt][2] += b1v.x; s[nt][3] += b1v.y;
        }
        if (kb + 31 > rg0) {
            #pragma unroll
            for (int nt = 0; nt < 4; nt++) {
                int c0 = kb + nt * 8 + 2 * t, c1 = c0 + 1;
                if (c0 > rg0) s[nt][0] = -1e30f;
                if (c1 > rg0) s[nt][1] = -1e30f;
                if (c0 > rg1) s[nt][2] = -1e30f;
                if (c1 > rg1) s[nt][3] = -1e30f;
            }
        }

        // ---- p = ex2(s), l, pack, O += P.V ----
        #pragma unroll
        for (int nt = 0; nt < 4; nt++) {
            s[nt][0] = ex2(s[nt][0]);
            s[nt][1] = ex2(s[nt][1]);
            s[nt][2] = ex2(s[nt][2]);
            s[nt][3] = ex2(s[nt][3]);
            l0 += s[nt][0] + s[nt][1];
            l1 += s[nt][2] + s[nt][3];
        }

        #pragma unroll
        for (int oc = 0; oc < 2; oc++) {
            unsigned pa0 = h2pack(s[2*oc][0],     s[2*oc][1]);
            unsigned pa1 = h2pack(s[2*oc][2],     s[2*oc][3]);
            unsigned pa2 = h2pack(s[2*oc + 1][0], s[2*oc + 1][1]);
            unsigned pa3 = h2pack(s[2*oc + 1][2], s[2*oc + 1][3]);
            #pragma unroll
            for (int p = 0; p < 4; p++) {
                unsigned vf[4];
                ldsm4(vf[0], vf[1], vf[2], vf[3],
                      vsh + ((p * 16 + bRow) * VHS + oc * 16 + bCol) * 2);
                mma16(o[2 * p],     pa0, pa1, pa2, pa3, vf[0], vf[1]);
                mma16(o[2 * p + 1], pa0, pa1, pa2, pa3, vf[2], vf[3]);
            }
        }
        __syncthreads();
    }

    // ---- epilogue ----
    l0 += __shfl_xor_sync(0xffffffffu, l0, 1);
    l0 += __shfl_xor_sync(0xffffffffu, l0, 2);
    l1 += __shfl_xor_sync(0xffffffffu, l1, 1);
    l1 += __shfl_xor_sync(0xffffffffu, l1, 2);
    float inv0 = 1.0f / l0, inv1 = 1.0f / l1;
    int r0 = rowoff + rg0, r1 = rowoff + rg1;
    #pragma unroll
    for (int vt = 0; vt < 8; vt++) {
        int col = h * DKn + vt * 8 + 2 * t;
        *(unsigned*)&Ah[(size_t)r0 * Dn + col] = h2pack(o[vt][0] * inv0, o[vt][1] * inv0);
        *(unsigned*)&Ah[(size_t)r1 * Dn + col] = h2pack(o[vt][2] * inv1, o[vt][3] * inv1);
    }
}

// ---------------- launch ----------------
extern "C" void kernel_launch(void* const* d_in, const int* in_sizes, int n_in,
                              void* d_out, int out_size)
{
    const float* x    = (const float*)d_in[0];
    const float* feat = (const float*)d_in[1];
    const float* req  = (const float*)d_in[2];
    const float* Wq   = (const float*)d_in[3];
    const float* bq   = (const float*)d_in[4];
    const float* Wk   = (const float*)d_in[5];
    const float* bk   = (const float*)d_in[6];
    const float* Wv   = (const float*)d_in[7];
    const float* bv   = (const float*)d_in[8];
    const float* Wo   = (const float*)d_in[9];
    const float* bo   = (const float*)d_in[10];
    float* out = (float*)d_out;

    __half *gXh, *gWth, *gQh, *gKh, *gVth, *gAh;
    float *gB;
    cudaGetSymbolAddress((void**)&gXh,  g_Xh);
    cudaGetSymbolAddress((void**)&gWth, g_Wth);
    cudaGetSymbolAddress((void**)&gQh,  g_Qh);
    cudaGetSymbolAddress((void**)&gKh,  g_Kh);
    cudaGetSymbolAddress((void**)&gVth, g_Vth);
    cudaGetSymbolAddress((void**)&gAh,  g_Ah);
    cudaGetSymbolAddress((void**)&gB,   g_Bias);
    const __half* gWtq = gWth;
    const __half* gWtk = gWth + Dn * Dn;
    const __half* gWtv = gWth + 2 * Dn * Dn;
    const __half* gWto = gWth + 3 * Dn * Dn;

    cudaFuncSetAttribute(gemm_f16,
                         cudaFuncAttributeMaxDynamicSharedMemorySize, GEMM_SMEM);
    cudaFuncSetAttribute(attn_f16,
                         cudaFuncAttributeMaxDynamicSharedMemorySize, ATT_SMEM);
    cudaFuncSetAttribute(bias_gemm,
                         cudaFuncAttributeMaxDynamicSharedMemorySize, BIAS_SMEM);

    const float QS = 1.4426950408889634f * 0.125f;

    round_x<<<4096, 256>>>(x);
    transpose_w<<<dim3(32, 32, 4), 256>>>(Wq, Wk, Wv, Wo);
    bias_gemm<<<dim3(16, 16, 2), 256, BIAS_SMEM>>>(req, feat, gB);

    gemm_f16<<<dim3(8, 32, 3), 256, GEMM_SMEM>>>(
        gXh, gWtq, gWtk, gWtv, bq, bk, bv,
        (float*)nullptr, gQh, gKh, gVth, 1, QS);

    attn_f16<<<dim3(32, Hn, Bn), 128, ATT_SMEM>>>(gQh, gKh, gVth, gB, gAh);

    gemm_f16<<<dim3(8, 32, 1), 256, GEMM_SMEM>>>(
        gAh, gWto, gWto, gWto, bo, bo, bo,
        out, (half*)nullptr, (half*)nullptr, (half*)nullptr, 0, 1.0f);
}

// round 17
// speedup vs baseline: 1.9398x; 1.0559x over previous
#include <cuda_runtime.h>
#include <cuda_fp16.h>
#include <math.h>

#define Bn 2
#define Sn 2048
#define Dn 1024
#define Hn 16
#define DKn 64
#define FDn 64
#define Mrows (Bn*Sn)

// ---------------- scratch ----------------
__device__ __half g_Xh[Mrows * Dn];
__device__ __half g_Wth[4][Dn * Dn];         // W^T [n][k] fp16
__device__ __half g_Qh[Mrows * Dn];          // Q * log2e/8
__device__ __half g_Kh[Mrows * Dn];
__device__ __half g_Vth[Dn * Mrows];         // V^T: [d][b*S+s]
__device__ __half g_Ah[Mrows * Dn];
__device__ float  g_Bias[(size_t)Bn * Sn * Sn];

__device__ __forceinline__ unsigned f2tf(float x) {
    unsigned r; asm("cvt.rna.tf32.f32 %0, %1;" : "=r"(r) : "f"(x)); return r;
}
__device__ __forceinline__ float ex2(float x) {
    float r; asm("ex2.approx.f32 %0, %1;" : "=f"(r) : "f"(x)); return r;
}
__device__ __forceinline__ unsigned h2pack(float lo, float hi) {
    unsigned r; asm("cvt.rn.f16x2.f32 %0, %1, %2;" : "=r"(r) : "f"(hi), "f"(lo)); return r;
}
__device__ __forceinline__ void mma8(float* c, unsigned a0, unsigned a1,
                                     unsigned a2, unsigned a3,
                                     unsigned b0, unsigned b1) {
    asm volatile("mma.sync.aligned.m16n8k8.row.col.f32.tf32.tf32.f32 "
                 "{%0,%1,%2,%3}, {%4,%5,%6,%7}, {%8,%9}, {%0,%1,%2,%3};"
                 : "+f"(c[0]), "+f"(c[1]), "+f"(c[2]), "+f"(c[3])
                 : "r"(a0), "r"(a1), "r"(a2), "r"(a3), "r"(b0), "r"(b1));
}
__device__ __forceinline__ void mma16(float* c, unsigned a0, unsigned a1,
                                      unsigned a2, unsigned a3,
                                      unsigned b0, unsigned b1) {
    asm volatile("mma.sync.aligned.m16n8k16.row.col.f32.f16.f16.f32 "
                 "{%0,%1,%2,%3}, {%4,%5,%6,%7}, {%8,%9}, {%0,%1,%2,%3};"
                 : "+f"(c[0]), "+f"(c[1]), "+f"(c[2]), "+f"(c[3])
                 : "r"(a0), "r"(a1), "r"(a2), "r"(a3), "r"(b0), "r"(b1));
}
__device__ __forceinline__ void ldsm4(unsigned& r0, unsigned& r1,
                                      unsigned& r2, unsigned& r3, unsigned addr) {
    asm volatile("ldmatrix.sync.aligned.m8n8.x4.shared.b16 {%0,%1,%2,%3}, [%4];"
                 : "=r"(r0), "=r"(r1), "=r"(r2), "=r"(r3) : "r"(addr));
}
__device__ __forceinline__ void cp16(unsigned dst, const void* src) {
    asm volatile("cp.async.cg.shared.global [%0], [%1], 16;" :: "r"(dst), "l"(src));
}

// ---------------- x -> fp16 ----------------
__global__ __launch_bounds__(256) void round_x(const float* __restrict__ x) {
    int idx = blockIdx.x * 256 + threadIdx.x;
    float4 v = ((const float4*)x)[idx];
    ((uint2*)g_Xh)[idx] = make_uint2(h2pack(v.x, v.y), h2pack(v.z, v.w));
}

// ---------------- W -> W^T fp16 ----------------
__global__ __launch_bounds__(256) void transpose_w(
    const float* __restrict__ Wq, const float* __restrict__ Wk,
    const float* __restrict__ Wv, const float* __restrict__ Wo)
{
    __shared__ float ts[32][33];
    int w = blockIdx.z;
    const float* W = (w == 0) ? Wq : (w == 1) ? Wk : (w == 2) ? Wv : Wo;
    __half* Wt = g_Wth[w];
    int k0 = blockIdx.x * 32, n0 = blockIdx.y * 32;
    int j = threadIdx.x & 31, i = threadIdx.x >> 5;
    #pragma unroll
    for (int p = 0; p < 4; p++)
        ts[i + 8 * p][j] = W[(size_t)(k0 + i + 8 * p) * Dn + n0 + j];
    __syncthreads();
    #pragma unroll
    for (int p = 0; p < 4; p++)
        Wt[(size_t)(n0 + i + 8 * p) * Dn + k0 + j] = __float2half(ts[j][i + 8 * p]);
}

// ---------------- bias GEMM (fused l2norm, tf32) ----------------
#define FST 72
#define BIAS_SMEM (2 * 128 * FST * 4)
__global__ __launch_bounds__(256) void bias_gemm(
    const float* __restrict__ Rq, const float* __restrict__ Fq, float* __restrict__ Bias)
{
    if (blockIdx.x > blockIdx.y) return;
    extern __shared__ unsigned bsm[];
    unsigned* As = bsm;
    unsigned* Bs = bsm + 128 * FST;

    int tid = threadIdx.x, lane = tid & 31, warp = tid >> 5;
    int g = lane >> 2, t = lane & 3;
    int wm = warp >> 2, wn = warp & 3;
    int i0 = blockIdx.y * 128, j0 = blockIdx.x * 128, bz = blockIdx.z;
    const float* R = Rq + (size_t)bz * Sn * FDn;
    const float* F = Fq + (size_t)bz * Sn * FDn;

    for (int i = tid; i < 128 * 16; i += 256) {
        int r = i >> 4, d4 = (i & 15) * 4;
        *(float4*)((float*)&As[r * FST + d4]) = *(const float4*)&R[(size_t)(i0 + r) * FDn + d4];
        *(float4*)((float*)&Bs[r * FST + d4]) = *(const float4*)&F[(size_t)(j0 + r) * FDn + d4];
    }
    __syncthreads();

    {
        float* rowp = (tid < 128) ? (float*)&As[tid * FST] : (float*)&Bs[(tid - 128) * FST];
        float ss = 0.0f;
        #pragma unroll
        for (int i = 0; i < 16; i++) {
            float4 v = *(const float4*)&rowp[i * 4];
            ss += v.x * v.x + v.y * v.y + v.z * v.z + v.w * v.w;
        }
        float inv = 1.0f / fmaxf(sqrtf(ss), 1e-12f);
        #pragma unroll
        for (int i = 0; i < 16; i++) {
            float4 v = *(const float4*)&rowp[i * 4];
            *(uint4*)&rowp[i * 4] =
                make_uint4(f2tf(v.x * inv), f2tf(v.y * inv), f2tf(v.z * inv), f2tf(v.w * inv));
        }
    }
    __syncthreads();

    float acc[4][4][4];
    #pragma unroll
    for (int i = 0; i < 4; i++)
        #pragma unroll
        for (int j = 0; j < 4; j++)
            #pragma unroll
            for (int r = 0; r < 4; r++) acc[i][j][r] = 0.0f;

    #pragma unroll
    for (int oct = 0; oct < 8; oct++) {
        int kk = oct * 8 + 2 * t;
        #pragma unroll
        for (int mt = 0; mt < 4; mt++) {
            int r = (wm * 64 + mt * 16 + g) * FST + kk;
            uint2 lo = *(const uint2*)&As[r];
            uint2 hi = *(const uint2*)&As[r + 8 * FST];
            #pragma unroll
            for (int nt = 0; nt < 4; nt++) {
                uint2 bb = *(const uint2*)&Bs[(wn * 32 + nt * 8 + g) * FST + kk];
                mma8(acc[mt][nt], lo.x, hi.x, lo.y, hi.y, bb.x, bb.y);
            }
        }
    }

    const float L2E = 1.4426950408889634f;
    float* C = Bias + (size_t)bz * Sn * Sn;
    #pragma unroll
    for (int mt = 0; mt < 4; mt++) {
        int row = i0 + wm * 64 + mt * 16 + g;
        #pragma unroll
        for (int nt = 0; nt < 4; nt++) {
            int col = j0 + wn * 32 + nt * 8 + 2 * t;
            *(float2*)&C[(size_t)row * Sn + col] =
                make_float2(acc[mt][nt][0] * L2E, acc[mt][nt][1] * L2E);
            *(float2*)&C[(size_t)(row + 8) * Sn + col] =
                make_float2(acc[mt][nt][2] * L2E, acc[mt][nt][3] * L2E);
        }
    }
}

// ---------------- fp16 GEMM: k-chunk 64, 2-stage, ldmatrix ----------------
#define GHS 72                              // halves per smem row (64+8)
#define GROW 144                            // bytes per row
#define GSTB 36864                          // bytes per stage (A 18432 + B 18432)
#define GEMM_SMEM (2 * GSTB)                // 73728

#define GF_CPA(stage, k0) do {                                                \
    unsigned a0_ = sbase + (stage) * GSTB;                                    \
    unsigned b0_ = a0_ + 18432;                                               \
    _Pragma("unroll")                                                         \
    for (int p = 0; p < 4; p++) { int c = tid + 256 * p;                      \
        int r = c >> 3, ch = c & 7;                                           \
        cp16(a0_ + r * GROW + ch * 16, &Ag[(size_t)(m0 + r) * Dn + (k0) + ch * 8]); } \
    _Pragma("unroll")                                                         \
    for (int p = 0; p < 4; p++) { int c = tid + 256 * p;                      \
        int r = c >> 3, ch = c & 7;                                           \
        cp16(b0_ + r * GROW + ch * 16, &Wt[(size_t)(n0 + r) * Dn + (k0) + ch * 8]); } \
    asm volatile("cp.async.commit_group;");                                   \
} while (0)

__global__ __launch_bounds__(256, 2) void gemm_f16(
    const __half* __restrict__ Ag,
    const __half* __restrict__ Wt0, const __half* __restrict__ Wt1, const __half* __restrict__ Wt2,
    const float* __restrict__ c0p, const float* __restrict__ c1p, const float* __restrict__ c2p,
    float* __restrict__ Cf,
    __half* __restrict__ Ch0, __half* __restrict__ Ch1, __half* __restrict__ Ch2,
    int qkv, float qscale)
{
    const __half* __restrict__ Wt  = (blockIdx.z == 0) ? Wt0 : (blockIdx.z == 1) ? Wt1 : Wt2;
    const float* __restrict__ bias = (blockIdx.z == 0) ? c0p : (blockIdx.z == 1) ? c1p : c2p;
    __half* __restrict__ Ch        = (blockIdx.z == 0) ? Ch0 : (blockIdx.z == 1) ? Ch1 : Ch2;
    int emode = qkv ? ((blockIdx.z == 2) ? 2 : 1) : 0;
    float scale = (qkv && blockIdx.z == 0) ? qscale : 1.0f;

    extern __shared__ char gsm[];
    unsigned sbase = (unsigned)__cvta_generic_to_shared(gsm);

    int tid = threadIdx.x, lane = tid & 31, warp = tid >> 5;
    int g = lane >> 2, t = lane & 3;
    int l8 = lane & 7, quad = lane >> 3;
    int wm = warp >> 2, wn = warp & 3;
    int m0 = blockIdx.y * 128, n0 = blockIdx.x * 128;

    int aRow = (quad & 1) * 8 + l8, aCol = (quad >> 1) * 8;
    int bRow = (quad >> 1) * 8 + l8, bCol = (quad & 1) * 8;

    float acc[4][4][4];
    #pragma unroll
    for (int i = 0; i < 4; i++)
        #pragma unroll
        for (int j = 0; j < 4; j++)
            #pragma unroll
            for (int r = 0; r < 4; r++) acc[i][j][r] = 0.0f;

    GF_CPA(0, 0);

    for (int it = 0; it < 16; ++it) {
        asm volatile("cp.async.wait_group 0;");
        __syncthreads();
        if (it + 1 < 16) GF_CPA((it + 1) & 1, (it + 1) * 64);

        unsigned sA = sbase + (it & 1) * GSTB;
        unsigned sB = sA + 18432;
        #pragma unroll
        for (int kc = 0; kc < 4; ++kc) {
            unsigned a[4][4], bfr[4][2];
            #pragma unroll
            for (int mt = 0; mt < 4; ++mt)
                ldsm4(a[mt][0], a[mt][1], a[mt][2], a[mt][3],
                      sA + ((wm * 64 + mt * 16 + aRow) * GHS + kc * 16 + aCol) * 2);
            #pragma unroll
            for (int p = 0; p < 2; ++p)
                ldsm4(bfr[2 * p][0], bfr[2 * p][1], bfr[2 * p + 1][0], bfr[2 * p + 1][1],
                      sB + ((wn * 32 + p * 16 + bRow) * GHS + kc * 16 + bCol) * 2);
            #pragma unroll
            for (int nt = 0; nt < 4; ++nt)
                #pragma unroll
                for (int mt = 0; mt < 4; ++mt)
                    mma16(acc[mt][nt], a[mt][0], a[mt][1], a[mt][2], a[mt][3],
                          bfr[nt][0], bfr[nt][1]);
        }
    }

    #pragma unroll
    for (int mt = 0; mt < 4; ++mt) {
        int row = m0 + wm * 64 + mt * 16 + g;
        #pragma unroll
        for (int nt = 0; nt < 4; ++nt) {
            int col = n0 + wn * 32 + nt * 8 + 2 * t;
            float b0 = bias[col], b1 = bias[col + 1];
            float x0 = acc[mt][nt][0] + b0, x1 = acc[mt][nt][1] + b1;
            float x2 = acc[mt][nt][2] + b0, x3 = acc[mt][nt][3] + b1;
            if (emode == 0) {
                *(float2*)&Cf[(size_t)row * Dn + col]       = make_float2(x0, x1);
                *(float2*)&Cf[(size_t)(row + 8) * Dn + col] = make_float2(x2, x3);
            } else if (emode == 1) {
                *(unsigned*)&Ch[(size_t)row * Dn + col]       = h2pack(x0 * scale, x1 * scale);
                *(unsigned*)&Ch[(size_t)(row + 8) * Dn + col] = h2pack(x2 * scale, x3 * scale);
            } else {
                Ch[(size_t)col * Mrows + row]           = __float2half(x0);
                Ch[(size_t)(col + 1) * Mrows + row]     = __float2half(x1);
                Ch[(size_t)col * Mrows + row + 8]       = __float2half(x2);
                Ch[(size_t)(col + 1) * Mrows + row + 8] = __float2half(x3);
            }
        }
    }
}

// ---------------- fp16 flash attention with ldmatrix fragments ----------------
#define KHS 72
#define VHS 40
#define BFS 40
#define KSB 4608
#define VSB 5120
#define BSB 10240
#define STGB (KSB + VSB + BSB)
#define ATT_SMEM (2 * STGB)

#define ISSUE_KV(stage, kb) do {                                               \
    unsigned ks0 = abase + (stage) * STGB;                                     \
    unsigned vs0 = ks0 + KSB;                                                  \
    unsigned bs0 = vs0 + VSB;                                                  \
    _Pragma("unroll")                                                          \
    for (int p = 0; p < 2; p++) { int c = tid + 128 * p;                       \
        int r = c >> 3, ch = c & 7;                                            \
        cp16(ks0 + r * 144 + ch * 16,                                          \
             &Kh[(size_t)(rowoff + (kb) + r) * Dn + h * DKn + ch * 8]); }      \
    _Pragma("unroll")                                                          \
    for (int p = 0; p < 2; p++) { int c = tid + 128 * p;                       \
        int r = c >> 2, ch = c & 3;                                            \
        cp16(vs0 + r * 80 + ch * 16,                                           \
             &Vth[(size_t)(h * DKn + r) * Mrows + rowoff + (kb) + ch * 8]); }  \
    _Pragma("unroll")                                                          \
    for (int p = 0; p < 4; p++) { int c = tid + 128 * p;                       \
        int r = c >> 3, d4 = (c & 7) * 4;                                      \
        cp16(bs0 + r * 160 + d4 * 4,                                           \
             &Bbp[(size_t)(qbase + r) * Sn + (kb) + d4]); }                    \
    asm volatile("cp.async.commit_group;");                                    \
} while (0)

__global__ __launch_bounds__(128, 4) void attn_f16(
    const __half* __restrict__ Qh, const __half* __restrict__ Kh,
    const __half* __restrict__ Vth, const float* __restrict__ Biasp,
    __half* __restrict__ Ah)
{
    extern __shared__ char asmem[];
    unsigned abase = (unsigned)__cvta_generic_to_shared(asmem);

    int tid = threadIdx.x, lane = tid & 31, warp = tid >> 5;
    int g = lane >> 2, t = lane & 3;
    int l8 = lane & 7, quad = lane >> 3;
    int qt = 31 - blockIdx.x;
    int h = blockIdx.y, b = blockIdx.z;
    int qbase = qt * 64, rowoff = b * Sn;
    int wq = warp * 16;
    const float* Bbp = Biasp + (size_t)b * Sn * Sn;

    int aRow = (quad & 1) * 8 + l8, aCol = (quad >> 1) * 8;
    int bRow = (quad >> 1) * 8 + l8, bCol = (quad & 1) * 8;

    #pragma unroll
    for (int p = 0; p < 4; p++) {
        int c = tid + 128 * p;
        int r = c >> 3, ch = c & 7;
        cp16(abase + r * 144 + ch * 16,
             &Qh[(size_t)(rowoff + qbase + r) * Dn + h * DKn + ch * 8]);
    }
    asm volatile("cp.async.commit_group;");
    asm volatile("cp.async.wait_group 0;");
    __syncthreads();

    unsigned qreg[4][4];
    #pragma unroll
    for (int o = 0; o < 4; o++)
        ldsm4(qreg[o][0], qreg[o][1], qreg[o][2], qreg[o][3],
              abase + ((wq + aRow) * KHS + o * 16 + aCol) * 2);
    __syncthreads();

    float o[8][4];
    #pragma unroll
    for (int vt = 0; vt < 8; vt++)
        #pragma unroll
        for (int j = 0; j < 4; j++) o[vt][j] = 0.0f;
    float l0 = 0.0f, l1 = 0.0f;

    int rg0 = qbase + wq + g, rg1 = rg0 + 8;
    int jmax = 2 * qt + 1;

    ISSUE_KV(0, 0);

    for (int jt = 0; jt <= jmax; jt++) {
        int cur = jt & 1;
        if (jt < jmax) {
            ISSUE_KV(cur ^ 1, (jt + 1) * 32);
            asm volatile("cp.async.wait_group 1;");
        } else {
            asm volatile("cp.async.wait_group 0;");
        }
        __syncthreads();

        unsigned ksh = abase + cur * STGB;
        unsigned vsh = ksh + KSB;
        const float* Bf = (const float*)(asmem + cur * STGB + KSB + VSB);
        int kb = jt * 32;

        float s[4][4];
        #pragma unroll
        for (int nt = 0; nt < 4; nt++)
            #pragma unroll
            for (int j = 0; j < 4; j++) s[nt][j] = 0.0f;

        #pragma unroll
        for (int oc = 0; oc < 4; oc++) {
            unsigned kf[4][2];
            #pragma unroll
            for (int p = 0; p < 2; p++)
                ldsm4(kf[2 * p][0], kf[2 * p][1], kf[2 * p + 1][0], kf[2 * p + 1][1],
                      ksh + ((p * 16 + bRow) * KHS + oc * 16 + bCol) * 2);
            #pragma unroll
            for (int nt = 0; nt < 4; nt++)
                mma16(s[nt], qreg[oc][0], qreg[oc][1], qreg[oc][2], qreg[oc][3],
                      kf[nt][0], kf[nt][1]);
        }

        #pragma unroll
        for (int nt = 0; nt < 4; nt++) {
            float2 b0v = *(const float2*)&Bf[(wq + g) * BFS + nt * 8 + 2 * t];
            float2 b1v = *(const float2*)&Bf[(wq + g + 8) * BFS + nt * 8 + 2 * t];
            s[nt][0] += b0v.x; s[nt][1] += b0v.y;
            s[nt][2] += b1v.x; s[nt][3] += b1v.y;
        }
        if (kb + 31 > rg0) {
            #pragma unroll
            for (int nt = 0; nt < 4; nt++) {
                int c0 = kb + nt * 8 + 2 * t, c1 = c0 + 1;
                if (c0 > rg0) s[nt][0] = -1e30f;
                if (c1 > rg0) s[nt][1] = -1e30f;
                if (c0 > rg1) s[nt][2] = -1e30f;
                if (c1 > rg1) s[nt][3] = -1e30f;
            }
        }

        #pragma unroll
        for (int nt = 0; nt < 4; nt++) {
            s[nt][0] = ex2(s[nt][0]);
            s[nt][1] = ex2(s[nt][1]);
            s[nt][2] = ex2(s[nt][2]);
            s[nt][3] = ex2(s[nt][3]);
            l0 += s[nt][0] + s[nt][1];
            l1 += s[nt][2] + s[nt][3];
        }

        #pragma unroll
        for (int oc = 0; oc < 2; oc++) {
            unsigned pa0 = h2pack(s[2*oc][0],     s[2*oc][1]);
            unsigned pa1 = h2pack(s[2*oc][2],     s[2*oc][3]);
            unsigned pa2 = h2pack(s[2*oc + 1][0], s[2*oc + 1][1]);
            unsigned pa3 = h2pack(s[2*oc + 1][2], s[2*oc + 1][3]);
            #pragma unroll
            for (int p = 0; p < 4; p++) {
                unsigned vf[4];
                ldsm4(vf[0], vf[1], vf[2], vf[3],
                      vsh + ((p * 16 + bRow) * VHS + oc * 16 + bCol) * 2);
                mma16(o[2 * p],     pa0, pa1, pa2, pa3, vf[0], vf[1]);
                mma16(o[2 * p + 1], pa0, pa1, pa2, pa3, vf[2], vf[3]);
            }
        }
        __syncthreads();
    }

    l0 += __shfl_xor_sync(0xffffffffu, l0, 1);
    l0 += __shfl_xor_sync(0xffffffffu, l0, 2);
    l1 += __shfl_xor_sync(0xffffffffu, l1, 1);
    l1 += __shfl_xor_sync(0xffffffffu, l1, 2);
    float inv0 = 1.0f / l0, inv1 = 1.0f / l1;
    int r0 = rowoff + rg0, r1 = rowoff + rg1;
    #pragma unroll
    for (int vt = 0; vt < 8; vt++) {
        int col = h * DKn + vt * 8 + 2 * t;
        *(unsigned*)&Ah[(size_t)r0 * Dn + col] = h2pack(o[vt][0] * inv0, o[vt][1] * inv0);
        *(unsigned*)&Ah[(size_t)r1 * Dn + col] = h2pack(o[vt][2] * inv1, o[vt][3] * inv1);
    }
}

// ---------------- launch ----------------
extern "C" void kernel_launch(void* const* d_in, const int* in_sizes, int n_in,
                              void* d_out, int out_size)
{
    const float* x    = (const float*)d_in[0];
    const float* feat = (const float*)d_in[1];
    const float* req  = (const float*)d_in[2];
    const float* Wq   = (const float*)d_in[3];
    const float* bq   = (const float*)d_in[4];
    const float* Wk   = (const float*)d_in[5];
    const float* bk   = (const float*)d_in[6];
    const float* Wv   = (const float*)d_in[7];
    const float* bv   = (const float*)d_in[8];
    const float* Wo   = (const float*)d_in[9];
    const float* bo   = (const float*)d_in[10];
    float* out = (float*)d_out;

    __half *gXh, *gWth, *gQh, *gKh, *gVth, *gAh;
    float *gB;
    cudaGetSymbolAddress((void**)&gXh,  g_Xh);
    cudaGetSymbolAddress((void**)&gWth, g_Wth);
    cudaGetSymbolAddress((void**)&gQh,  g_Qh);
    cudaGetSymbolAddress((void**)&gKh,  g_Kh);
    cudaGetSymbolAddress((void**)&gVth, g_Vth);
    cudaGetSymbolAddress((void**)&gAh,  g_Ah);
    cudaGetSymbolAddress((void**)&gB,   g_Bias);
    const __half* gWtq = gWth;
    const __half* gWtk = gWth + Dn * Dn;
    const __half* gWtv = gWth + 2 * Dn * Dn;
    const __half* gWto = gWth + 3 * Dn * Dn;

    cudaFuncSetAttribute(gemm_f16,
                         cudaFuncAttributeMaxDynamicSharedMemorySize, GEMM_SMEM);
    cudaFuncSetAttribute(attn_f16,
                         cudaFuncAttributeMaxDynamicSharedMemorySize, ATT_SMEM);
    cudaFuncSetAttribute(bias_gemm,
                         cudaFuncAttributeMaxDynamicSharedMemorySize, BIAS_SMEM);

    const float QS = 1.4426950408889634f * 0.125f;

    round_x<<<4096, 256>>>(x);
    transpose_w<<<dim3(32, 32, 4), 256>>>(Wq, Wk, Wv, Wo);
    bias_gemm<<<dim3(16, 16, 2), 256, BIAS_SMEM>>>(req, feat, gB);

    gemm_f16<<<dim3(8, 32, 3), 256, GEMM_SMEM>>>(
        gXh, gWtq, gWtk, gWtv, bq, bk, bv,
        (float*)nullptr, gQh, gKh, gVth, 1, QS);

    attn_f16<<<dim3(32, Hn, Bn), 128, ATT_SMEM>>>(gQh, gKh, gVth, gB, gAh);

    gemm_f16<<<dim3(8, 32, 1), 256, GEMM_SMEM>>>(
        gAh, gWto, gWto, gWto, bo, bo, bo,
        out, (half*)nullptr, (half*)nullptr, (half*)nullptr, 0, 1.0f);
}